// round 12
// baseline (speedup 1.0000x reference)
#include <cuda_runtime.h>
#include <cuda_bf16.h>
#include <stdint.h>
#include <math.h>

#define BHN 32          // B*H
#define LN 1024
#define DN 64
#define LMAXN 2048
#define NF 4
#define PARTN (BHN * NF * LN)   // 131072
#define PI_F 3.14159265358979323846f

// ---------------- device scratch (static allocation only) ----------------
__device__ __nv_bfloat16 g_gram[(size_t)BHN * LN * LN];  // 64 MB
__device__ __nv_bfloat16 g_qk[4][(size_t)BHN * 16 * 4096]; // bf16 swizzled tiles qr,qi,kr,ki
__device__ float g_a[NF * LN];
__device__ float g_p1[(size_t)8 * PARTN];             // s1 partials, slot-major (8 slots)
__device__ float g_epr[LN * DN];
__device__ float g_epi[LN * DN];
__device__ __nv_bfloat16 g_vtr[(size_t)BHN * DN * LN];
__device__ __nv_bfloat16 g_vti[(size_t)BHN * DN * LN];
__device__ float g_cspr[16 * BHN * DN];
__device__ float g_cspi[16 * BHN * DN];

__device__ __forceinline__ uint32_t smem_u32(const void* p) {
    uint32_t a;
    asm("{ .reg .u64 t; cvta.to.shared.u64 t, %1; cvt.u32.u64 %0, t; }" : "=r"(a) : "l"(p));
    return a;
}
__device__ __forceinline__ void sts32(uint32_t a, uint32_t v) {
    asm volatile("st.shared.b32 [%0], %1;" :: "r"(a), "r"(v));
}

#define LDSM_X4(r, a) \
    asm volatile("ldmatrix.sync.aligned.m8n8.x4.shared.b16 {%0,%1,%2,%3}, [%4];" \
        : "=r"((r)[0]), "=r"((r)[1]), "=r"((r)[2]), "=r"((r)[3]) : "r"(a))
#define MMA16816(d, a, b) \
    asm volatile("mma.sync.aligned.m16n8k16.row.col.f32.bf16.bf16.f32 " \
        "{%0,%1,%2,%3},{%4,%5,%6,%7},{%8,%9},{%0,%1,%2,%3};" \
        : "+f"((d)[0]), "+f"((d)[1]), "+f"((d)[2]), "+f"((d)[3]) \
        : "r"((a)[0]), "r"((a)[1]), "r"((a)[2]), "r"((a)[3]), "r"((b)[0]), "r"((b)[1]))
#define CPASYNC16(dst, src) \
    asm volatile("cp.async.cg.shared.global [%0], [%1], 16;" :: "r"(dst), "l"(src))
#define CPCOMMIT() asm volatile("cp.async.commit_group;" ::: "memory")
#define CPWAIT0()  asm volatile("cp.async.wait_group 0;" ::: "memory")
#define CPWAIT1()  asm volatile("cp.async.wait_group 1;" ::: "memory")

// ---------------- P1+P2 merged: a_f[l] patterns + expert pattern ----------
__global__ __launch_bounds__(256) void prep_kernel() {
    int tid = threadIdx.x;
    if (blockIdx.x < NF) {
        const float freqs[NF] = {1.0f, 0.5f, 0.25f, 0.1f};
        int f = blockIdx.x;
        float step = 2.f * PI_F * freqs[f] / (float)(LMAXN - 1);
        float s = 0.f;
        for (int j = tid; j < LMAXN; j += 256) {
            float t = step * (float)j;
            s += 3.f + 2.f * cosf(t) + 2.f * cosf(0.5f * t) + 2.f * cosf(1.5f * t);
        }
        __shared__ float red[256];
        red[tid] = s;
        __syncthreads();
        for (int o = 128; o > 0; o >>= 1) {
            if (tid < o) red[tid] += red[tid + o];
            __syncthreads();
        }
        float norm2 = red[0];
        for (int l = tid; l < LN; l += 256) {
            float t = step * (float)l;
            float v = 3.f + 2.f * cosf(t) + 2.f * cosf(0.5f * t) + 2.f * cosf(1.5f * t);
            v = fmaxf(v, 0.f);
            g_a[f * LN + l] = sqrtf(v / norm2);
        }
    } else {
        int idx = (blockIdx.x - NF) * 256 + tid;
        if (idx >= LN * DN) return;
        int l = idx / DN, d = idx % DN;
        float t = 2.f * PI_F * (float)l / (float)(LMAXN - 1);
        float pd = 2.f * PI_F * (float)d / (float)DN;
        float sr = 0.f, si = 0.f;
        for (int i = 0; i < 8; i++) {
            float base = 0.1f * (float)i;
#pragma unroll
            for (int a = 0; a < 3; a++) {
                float fr = (0.3f - 0.1f * (float)a) + base;
                float ang = fr * t + pd;
                sr += cosf(ang);
                si += sinf(ang);
            }
        }
        const float C = (1.f / sqrtf((float)LMAXN)) / (sqrtf(3.f) * sqrtf(8.f));
        g_epr[idx] = sr * C;
        g_epi[idx] = si * C;
    }
}

// ---------------- P2b+P3 fused: Q/K bf16 convert  AND  V^T + colsum -------
__global__ __launch_bounds__(256) void convert_kernel(
    const float* __restrict__ Qr, const float* __restrict__ Qi,
    const float* __restrict__ Kr, const float* __restrict__ Ki,
    const float* __restrict__ Vr, const float* __restrict__ Vi) {
    __shared__ float sr[64][65], si[64][65];
    __shared__ float csr4[4][64], csi4[4][64];
    int tile = blockIdx.x, bh = blockIdx.y, arr = blockIdx.z;
    int tid = threadIdx.x;
    if (arr < 4) {
        const float* src = (arr == 0 ? Qr : arr == 1 ? Qi : arr == 2 ? Kr : Ki)
                           + ((size_t)bh * LN + (size_t)tile * 64) * DN;
        char* dst = (char*)(g_qk[arr] + ((size_t)(bh * 16 + tile)) * 4096);
#pragma unroll
        for (int k = 0; k < 4; k++) {
            int i = tid + k * 256;
            int row = i >> 4, c4 = i & 15;
            float4 v = *(const float4*)(src + row * 64 + c4 * 4);
            uint32_t p0, p1;
            asm("cvt.rn.bf16x2.f32 %0, %1, %2;" : "=r"(p0) : "f"(v.y), "f"(v.x));
            asm("cvt.rn.bf16x2.f32 %0, %1, %2;" : "=r"(p1) : "f"(v.w), "f"(v.z));
            uint32_t off = (uint32_t)(row * 128 + c4 * 8);
            off ^= ((uint32_t)(row & 7) << 4);
            *(uint32_t*)(dst + off) = p0;
            *(uint32_t*)(dst + off + 4) = p1;
        }
        return;
    }
    int mt = tile;
    const float* vrb = Vr + ((size_t)bh * LN + (size_t)mt * 64) * DN;
    const float* vib = Vi + ((size_t)bh * LN + (size_t)mt * 64) * DN;
#pragma unroll
    for (int k = 0; k < 16; k++) {
        int i = tid + k * 256;
        int m = i >> 6, d = i & 63;
        sr[m][d] = vrb[i];
        si[m][d] = vib[i];
    }
    __syncthreads();
#pragma unroll
    for (int k = 0; k < 8; k++) {
        int i = tid + k * 256;
        int d = i >> 5, mp = i & 31, m = mp * 2;
        uint32_t pr, pi;
        asm("cvt.rn.bf16x2.f32 %0, %1, %2;" : "=r"(pr) : "f"(sr[m + 1][d]), "f"(sr[m][d]));
        asm("cvt.rn.bf16x2.f32 %0, %1, %2;" : "=r"(pi) : "f"(si[m + 1][d]), "f"(si[m][d]));
        size_t o = (size_t)bh * DN * LN + (size_t)d * LN + mt * 64 + m;
        *(uint32_t*)&g_vtr[o] = pr;
        *(uint32_t*)&g_vti[o] = pi;
    }
    {
        int d = tid & 63, seg = tid >> 6;
        float aR = 0.f, aI = 0.f;
#pragma unroll
        for (int j = 0; j < 16; j++) {
            aR += sr[seg * 16 + j][d];
            aI += si[seg * 16 + j][d];
        }
        csr4[seg][d] = aR; csi4[seg][d] = aI;
    }
    __syncthreads();
    if (tid < 64) {
        int d = tid;
        g_cspr[(mt * BHN + bh) * DN + d] = csr4[0][d] + csr4[1][d] + csr4[2][d] + csr4[3][d];
        g_cspi[(mt * BHN + bh) * DN + d] = csi4[0][d] + csi4[1][d] + csi4[2][d] + csi4[3][d];
    }
}

// ---- 8KB tile prefetch: 2 cp.async.16B per thread (256 thr) ----
__device__ __forceinline__ void prefetch_tile(uint32_t dst, const char* src, int tid) {
#pragma unroll
    for (int i = 0; i < 2; i++) {
        int o = (tid + i * 256) * 16;
        CPASYNC16(dst + o, src + o);
    }
}

// ---------------- A: gram; s1 moment computed ON the tensor core ----------
__global__ __launch_bounds__(256, 2) void gram_mma_kernel() {
    __shared__ __align__(16) uint32_t s_q[2][2048];      // qr, qi tiles
    __shared__ __align__(16) uint32_t s_k[2][2][2048];   // [buf][kr/ki]
    __shared__ float sAm[NF][256];

    int tid = threadIdx.x;
    int lane = tid & 31, w = tid >> 5;
    int wr = w >> 1, wc = w & 1;
    int mtg = blockIdx.x, lt = blockIdx.y, bh = blockIdx.z;

    const char* qrt = (const char*)(g_qk[0] + ((size_t)(bh * 16 + lt)) * 4096);
    const char* qit = (const char*)(g_qk[1] + ((size_t)(bh * 16 + lt)) * 4096);
    const char* krb = (const char*)(g_qk[2] + ((size_t)(bh * 16 + mtg * 4)) * 4096);
    const char* kib = (const char*)(g_qk[3] + ((size_t)(bh * 16 + mtg * 4)) * 4096);

    uint32_t aq0 = smem_u32(s_q[0]), aq1 = smem_u32(s_q[1]);

    prefetch_tile(aq0, qrt, tid);
    prefetch_tile(aq1, qit, tid);
    prefetch_tile(smem_u32(s_k[0][0]), krb, tid);
    prefetch_tile(smem_u32(s_k[0][1]), kib, tid);
    CPCOMMIT();
#pragma unroll
    for (int i = tid; i < NF * 256; i += 256)
        sAm[i >> 8][i & 255] = g_a[(i >> 8) * LN + mtg * 256 + (i & 255)];
    CPWAIT0();
    __syncthreads();

    int l16 = lane & 15, ac = lane >> 4;
    uint32_t aR[4][4], aI[4][4];
#pragma unroll
    for (int ks = 0; ks < 4; ks++) {
        int row = wr * 16 + l16;
        uint32_t off = (uint32_t)(row * 128 + ac * 16 + ks * 32);
        uint32_t sw = off ^ ((uint32_t)(row & 7) << 4);
        LDSM_X4(aR[ks], aq0 + sw);
        LDSM_X4(aI[ks], aq1 + sw);
    }

    int b_row = ((lane >> 4) << 3) + (lane & 7);
    int b_kh = (lane >> 3) & 1;
    int qrow = lane >> 2, qcol = (lane & 3) * 2;
    int fq = qrow;
    bool act = fq < NF;

    float sacc[4] = {0.f, 0.f, 0.f, 0.f};

    for (int it = 0; it < 4; it++) {
        int mt = mtg * 4 + it;
        if (it > 0) CPWAIT0();
        __syncthreads();
        if (it < 3) {
            prefetch_tile(smem_u32(s_k[(it + 1) & 1][0]), krb + (size_t)(it + 1) * 8192, tid);
            prefetch_tile(smem_u32(s_k[(it + 1) & 1][1]), kib + (size_t)(it + 1) * 8192, tid);
            CPCOMMIT();
        }

        uint32_t akr = smem_u32(s_k[it & 1][0]), aki = smem_u32(s_k[it & 1][1]);
        float cr[4][4] = {}, ci[4][4] = {};
#pragma unroll
        for (int ks = 0; ks < 4; ks++) {
            uint32_t bR[8], bI[8], bIn[8];
#pragma unroll
            for (int p = 0; p < 2; p++) {
                int row = wc * 32 + p * 16 + b_row;
                uint32_t off = (uint32_t)(row * 128 + b_kh * 16 + ks * 32);
                uint32_t sw = off ^ ((uint32_t)(row & 7) << 4);
                LDSM_X4(bR + p * 4, akr + sw);
                LDSM_X4(bI + p * 4, aki + sw);
            }
#pragma unroll
            for (int j = 0; j < 8; j++) bIn[j] = bI[j] ^ 0x80008000u;
#pragma unroll
            for (int ni = 0; ni < 4; ni++) {
                MMA16816(cr[ni], aR[ks], (bR + ni * 2));
                MMA16816(cr[ni], aI[ks], (bIn + ni * 2));
                MMA16816(ci[ni], aR[ks], (bI + ni * 2));
                MMA16816(ci[ni], aI[ks], (bR + ni * 2));
            }
        }

        __nv_bfloat16* gb = g_gram + (size_t)bh * LN * LN;
        int r0 = lt * 64 + wr * 16 + qrow;
#pragma unroll
        for (int ks2 = 0; ks2 < 2; ks2++) {
            uint32_t Afrag[4];
#pragma unroll
            for (int nio = 0; nio < 2; nio++) {
                int ni = ks2 * 2 + nio;
                float mg[4];
#pragma unroll
                for (int j = 0; j < 4; j++) {
                    float c = cr[ni][j], d = ci[ni][j];
                    float m2 = c * c + d * d;
                    float s;
                    asm("sqrt.approx.f32 %0, %1;" : "=f"(s) : "f"(m2));
                    mg[j] = s * 0.125f;
                }
                uint32_t p01, p23;
                asm("cvt.rn.bf16x2.f32 %0, %1, %2;" : "=r"(p01) : "f"(mg[1]), "f"(mg[0]));
                asm("cvt.rn.bf16x2.f32 %0, %1, %2;" : "=r"(p23) : "f"(mg[3]), "f"(mg[2]));
                int mcol = mt * 64 + wc * 32 + ni * 8 + qcol;
                *(uint32_t*)(gb + (size_t)r0 * LN + mcol) = p01;
                *(uint32_t*)(gb + (size_t)(r0 + 8) * LN + mcol) = p23;
                Afrag[nio * 2 + 0] = p01;
                Afrag[nio * 2 + 1] = p23;
            }
            int mb = it * 64 + wc * 32 + ks2 * 16;
            float a0 = 0.f, a1 = 0.f, a2 = 0.f, a3 = 0.f;
            if (act) {
                a0 = sAm[fq][mb + qcol];     a1 = sAm[fq][mb + qcol + 1];
                a2 = sAm[fq][mb + qcol + 8]; a3 = sAm[fq][mb + qcol + 9];
            }
            uint32_t Bfrag[2];
            asm("cvt.rn.bf16x2.f32 %0, %1, %2;" : "=r"(Bfrag[0]) : "f"(a1), "f"(a0));
            asm("cvt.rn.bf16x2.f32 %0, %1, %2;" : "=r"(Bfrag[1]) : "f"(a3), "f"(a2));
            MMA16816(sacc, Afrag, Bfrag);
        }
    }

    if ((lane & 3) < 2) {
        int slot = mtg * 2 + wc;
        int r0 = lt * 64 + wr * 16 + qrow;
        size_t base = (size_t)slot * PARTN + (size_t)bh * NF * LN;
        g_p1[base + (size_t)qcol * LN + r0] = sacc[0];
        g_p1[base + (size_t)(qcol + 1) * LN + r0] = sacc[1];
        g_p1[base + (size_t)qcol * LN + r0 + 8] = sacc[2];
        g_p1[base + (size_t)(qcol + 1) * LN + r0 + 8] = sacc[3];
    }
}

// ---- Vt tile prefetch (64 rows, swizzled; 128 thr) ----
__device__ __forceinline__ void prefetch_vt64(
    uint32_t dr, uint32_t di,
    const __nv_bfloat16* vtr, const __nv_bfloat16* vti, int mt, int tid) {
#pragma unroll
    for (int k = 0; k < 4; k++) {
        int i = tid + k * 128;           // 0..511
        int row = i >> 3, c16 = i & 7;
        uint32_t off = (uint32_t)(row * 128 + c16 * 16);
        uint32_t sw = off ^ ((uint32_t)(row & 7) << 4);
        CPASYNC16(dr + sw, (const char*)(vtr + (size_t)row * LN + mt * 64) + c16 * 16);
        CPASYNC16(di + sw, (const char*)(vti + (size_t)row * LN + mt * 64) + c16 * 16);
    }
}

// ---- g tile prefetch: 64 rows x 128B, plain layout (128 thr) ----
__device__ __forceinline__ void prefetch_g64(
    uint32_t dst, const __nv_bfloat16* gb, int mt, int tid) {
#pragma unroll
    for (int k = 0; k < 4; k++) {
        int i = tid + k * 128;           // 0..511
        int row = i >> 3, c16 = i & 7;
        CPASYNC16(dst + (uint32_t)(row * 128 + c16 * 16),
                  (const char*)(gb + (size_t)row * LN + mt * 64) + c16 * 16);
    }
}

// ---------------- C: 128 thr, 64 l-rows, g + Vt cp.async double-buffered --
__global__ __launch_bounds__(128) void attn_mma_kernel(float* __restrict__ out) {
    __shared__ __align__(16) uint32_t s_w[2048];        // dW bf16 64x64 swizzled
    __shared__ __align__(16) uint32_t s_vr[2][2048];
    __shared__ __align__(16) uint32_t s_vi[2][2048];
    __shared__ __align__(16) uint32_t s_g[2][2048];     // g tiles 64x64 bf16 plain
    __shared__ float s_c[NF][64];
    __shared__ float s_base[64];
    __shared__ float s_csr[64], s_csi[64];
    __shared__ float s_is[NF][64];

    int tid = threadIdx.x;
    int lane = tid & 31, w = tid >> 5;
    int wr = w >> 1, wc = w & 1;
    int lt = blockIdx.x, bh = blockIdx.y;       // 16 x 32

    uint32_t a_w = smem_u32(s_w);
    const __nv_bfloat16* vtr = g_vtr + (size_t)bh * DN * LN;
    const __nv_bfloat16* vti = g_vti + (size_t)bh * DN * LN;
    const __nv_bfloat16* gb = g_gram + (size_t)bh * LN * LN + (size_t)lt * 64 * LN;

    // prologue prefetch: g[0] + Vt[0]
    prefetch_g64(smem_u32(s_g[0]), gb, 0, tid);
    prefetch_vt64(smem_u32(s_vr[0]), smem_u32(s_vi[0]), vtr, vti, 0, tid);
    CPCOMMIT();

    // invS reduction: 8 slots
#pragma unroll
    for (int idx = tid; idx < NF * 64; idx += 128) {
        int f = idx >> 6, r = idx & 63;
        int lg = lt * 64 + r;
        const float* p = g_p1 + ((size_t)bh * NF + f) * LN + lg;
        float s1 = 0.f;
#pragma unroll
        for (int i = 0; i < 8; i++) s1 += p[(size_t)i * PARTN];
        float al = g_a[f * LN + lg];
        s_is[f][r] = 1.f / (1024.f + al * s1);
    }
    __syncthreads();
    if (tid < 64) {
        int lg = lt * 64 + tid;
        float b = 0.f;
#pragma unroll
        for (int f = 0; f < NF; f++) {
            float is = s_is[f][tid];
            s_c[f][tid] = is * g_a[f * LN + lg];
            b += is;
        }
        s_base[tid] = b;
        float csR = 0.f, csI = 0.f;
#pragma unroll
        for (int m2 = 0; m2 < 16; m2++) {
            csR += g_cspr[(m2 * BHN + bh) * DN + tid];
            csI += g_cspi[(m2 * BHN + bh) * DN + tid];
        }
        s_csr[tid] = csR;
        s_csi[tid] = csI;
    }

    float accr[2][4][4] = {}, acci[2][4][4] = {};

    int l16 = lane & 15, ac = lane >> 4;
    int bm0 = (tid & 31) * 2, lgrp = tid >> 5;  // 4 groups x 16 rows = 64
    int b_nii = (lane >> 4) & 1, b_kh = (lane >> 3) & 1, b_l8 = lane & 7;

    for (int mt = 0; mt < 16; mt++) {
        __syncthreads();          // prior iteration's buffer reads done
        if (mt < 15) {
            prefetch_g64(smem_u32(s_g[(mt + 1) & 1]), gb, mt + 1, tid);
            prefetch_vt64(smem_u32(s_vr[(mt + 1) & 1]), smem_u32(s_vi[(mt + 1) & 1]),
                          vtr, vti, mt + 1, tid);
            CPCOMMIT();
            CPWAIT1();            // group(mt) complete
        } else {
            CPWAIT0();
        }
        __syncthreads();          // group(mt) data visible
        // ---- build dW tile from smem g ----
        {
            uint32_t sg = smem_u32(s_g[mt & 1]);
            float am0[NF], am1[NF];
#pragma unroll
            for (int f = 0; f < NF; f++) {
                am0[f] = g_a[f * LN + mt * 64 + bm0];
                am1[f] = g_a[f * LN + mt * 64 + bm0 + 1];
            }
#pragma unroll 4
            for (int li = 0; li < 16; li++) {
                int l = lgrp * 16 + li;
                float dot0 = 0.f, dot1 = 0.f;
#pragma unroll
                for (int f = 0; f < NF; f++) {
                    float c = s_c[f][l];
                    dot0 = fmaf(c, am0[f], dot0);
                    dot1 = fmaf(c, am1[f], dot1);
                }
                uint32_t gp;
                asm volatile("ld.shared.b32 %0, [%1];"
                             : "=r"(gp) : "r"(sg + (uint32_t)(l * 128 + bm0 * 2)));
                float2 gf = __bfloat1622float2(*(__nv_bfloat162*)&gp);
                float w0 = dot0 * gf.x;
                float w1 = dot1 * gf.y;
                uint32_t p;
                asm("cvt.rn.bf16x2.f32 %0, %1, %2;" : "=r"(p) : "f"(w1), "f"(w0));
                uint32_t off = (uint32_t)(l * 128 + bm0 * 2);
                uint32_t sw = off ^ ((uint32_t)(l & 7) << 4);
                sts32(a_w + sw, p);
            }
        }
        __syncthreads();          // s_w ready
        uint32_t avr = smem_u32(s_vr[mt & 1]), avi = smem_u32(s_vi[mt & 1]);
#pragma unroll
        for (int ks = 0; ks < 4; ks++) {
            uint32_t aW[2][4];
#pragma unroll
            for (int mi = 0; mi < 2; mi++) {
                int row = wr * 32 + mi * 16 + l16;
                uint32_t off = (uint32_t)(row * 128 + ac * 16 + ks * 32);
                uint32_t sw = off ^ ((uint32_t)(row & 7) << 4);
                LDSM_X4(aW[mi], a_w + sw);
            }
#pragma unroll
            for (int ni2 = 0; ni2 < 2; ni2++) {
                uint32_t bR[4], bI[4];
                int row = wc * 32 + ni2 * 16 + b_nii * 8 + b_l8;
                uint32_t off = (uint32_t)(row * 128 + b_kh * 16 + ks * 32);
                uint32_t sw = off ^ ((uint32_t)(row & 7) << 4);
                LDSM_X4(bR, avr + sw);
                LDSM_X4(bI, avi + sw);
#pragma unroll
                for (int mi = 0; mi < 2; mi++) {
#pragma unroll
                    for (int h = 0; h < 2; h++) {
                        int ni = ni2 * 2 + h;
                        MMA16816(accr[mi][ni], aW[mi], (bR + h * 2));
                        MMA16816(acci[mi][ni], aW[mi], (bI + h * 2));
                    }
                }
            }
        }
    }

    int qrow = lane >> 2, qcol = (lane & 3) * 2;
    const size_t imag_off = (size_t)BHN * LN * DN;
    float* ob = out + (size_t)bh * LN * DN;
#pragma unroll
    for (int mi = 0; mi < 2; mi++) {
#pragma unroll
        for (int half = 0; half < 2; half++) {
            int lrow = wr * 32 + mi * 16 + half * 8 + qrow;
            int lg = lt * 64 + lrow;
            float base = s_base[lrow];
#pragma unroll
            for (int ni = 0; ni < 4; ni++) {
                int d = wc * 32 + ni * 8 + qcol;
                float ar0 = fmaf(base, s_csr[d], accr[mi][ni][half * 2]) * 0.5f;
                float ai0 = fmaf(base, s_csi[d], acci[mi][ni][half * 2]) * 0.5f;
                float ar1 = fmaf(base, s_csr[d + 1], accr[mi][ni][half * 2 + 1]) * 0.5f;
                float ai1 = fmaf(base, s_csi[d + 1], acci[mi][ni][half * 2 + 1]) * 0.5f;
                float2 er = *(const float2*)(g_epr + lg * DN + d);
                float2 ei = *(const float2*)(g_epi + lg * DN + d);
                float2 oR, oI;
                oR.x = ar0 * er.x - ai0 * ei.x;
                oI.x = ar0 * ei.x + ai0 * er.x;
                oR.y = ar1 * er.y - ai1 * ei.y;
                oI.y = ar1 * ei.y + ai1 * er.y;
                *(float2*)(ob + (size_t)lg * DN + d) = oR;
                *(float2*)(ob + imag_off + (size_t)lg * DN + d) = oI;
            }
        }
    }
}

// ---------------- launcher ----------------
extern "C" void kernel_launch(void* const* d_in, const int* in_sizes, int n_in,
                              void* d_out, int out_size) {
    (void)in_sizes; (void)n_in; (void)out_size;
    const float* Qr = (const float*)d_in[0];
    const float* Qi = (const float*)d_in[1];
    const float* Kr = (const float*)d_in[2];
    const float* Ki = (const float*)d_in[3];
    const float* Vr = (const float*)d_in[4];
    const float* Vi = (const float*)d_in[5];
    float* out = (float*)d_out;

    prep_kernel<<<NF + (LN * DN + 255) / 256, 256>>>();
    convert_kernel<<<dim3(16, BHN, 5), 256>>>(Qr, Qi, Kr, Ki, Vr, Vi);
    gram_mma_kernel<<<dim3(4, 16, BHN), 256>>>();
    attn_mma_kernel<<<dim3(16, BHN), 128>>>(out);
}

// round 13
// speedup vs baseline: 1.1104x; 1.1104x over previous
#include <cuda_runtime.h>
#include <cuda_bf16.h>
#include <stdint.h>
#include <math.h>

#define BHN 32          // B*H
#define LN 1024
#define DN 64
#define LMAXN 2048
#define NF 4
#define PARTN (BHN * NF * LN)   // 131072
#define PI_F 3.14159265358979323846f

// ---------------- device scratch (static allocation only) ----------------
__device__ __nv_bfloat16 g_gram[(size_t)BHN * LN * LN];  // 64 MB
__device__ __nv_bfloat16 g_qk[4][(size_t)BHN * 16 * 4096]; // bf16 swizzled tiles qr,qi,kr,ki
__device__ float g_a[NF * LN];
__device__ float g_p1[(size_t)8 * PARTN];             // s1 partials, slot-major (8 slots)
__device__ float g_epr[LN * DN];
__device__ float g_epi[LN * DN];
__device__ __nv_bfloat16 g_vtr[(size_t)BHN * DN * LN];
__device__ __nv_bfloat16 g_vti[(size_t)BHN * DN * LN];
__device__ float g_cspr[16 * BHN * DN];
__device__ float g_cspi[16 * BHN * DN];

__device__ __forceinline__ uint32_t smem_u32(const void* p) {
    uint32_t a;
    asm("{ .reg .u64 t; cvta.to.shared.u64 t, %1; cvt.u32.u64 %0, t; }" : "=r"(a) : "l"(p));
    return a;
}
__device__ __forceinline__ void sts32(uint32_t a, uint32_t v) {
    asm volatile("st.shared.b32 [%0], %1;" :: "r"(a), "r"(v));
}

#define LDSM_X4(r, a) \
    asm volatile("ldmatrix.sync.aligned.m8n8.x4.shared.b16 {%0,%1,%2,%3}, [%4];" \
        : "=r"((r)[0]), "=r"((r)[1]), "=r"((r)[2]), "=r"((r)[3]) : "r"(a))
#define MMA16816(d, a, b) \
    asm volatile("mma.sync.aligned.m16n8k16.row.col.f32.bf16.bf16.f32 " \
        "{%0,%1,%2,%3},{%4,%5,%6,%7},{%8,%9},{%0,%1,%2,%3};" \
        : "+f"((d)[0]), "+f"((d)[1]), "+f"((d)[2]), "+f"((d)[3]) \
        : "r"((a)[0]), "r"((a)[1]), "r"((a)[2]), "r"((a)[3]), "r"((b)[0]), "r"((b)[1]))
#define CPASYNC16(dst, src) \
    asm volatile("cp.async.cg.shared.global [%0], [%1], 16;" :: "r"(dst), "l"(src))
#define CPCOMMIT() asm volatile("cp.async.commit_group;" ::: "memory")
#define CPWAIT0()  asm volatile("cp.async.wait_group 0;" ::: "memory")
#define CPWAIT1()  asm volatile("cp.async.wait_group 1;" ::: "memory")

// ---------------- P1+P2 merged: a_f[l] patterns + expert pattern ----------
__global__ __launch_bounds__(256) void prep_kernel() {
    int tid = threadIdx.x;
    if (blockIdx.x < NF) {
        const float freqs[NF] = {1.0f, 0.5f, 0.25f, 0.1f};
        int f = blockIdx.x;
        float step = 2.f * PI_F * freqs[f] / (float)(LMAXN - 1);
        float s = 0.f;
        for (int j = tid; j < LMAXN; j += 256) {
            float t = step * (float)j;
            s += 3.f + 2.f * cosf(t) + 2.f * cosf(0.5f * t) + 2.f * cosf(1.5f * t);
        }
        __shared__ float red[256];
        red[tid] = s;
        __syncthreads();
        for (int o = 128; o > 0; o >>= 1) {
            if (tid < o) red[tid] += red[tid + o];
            __syncthreads();
        }
        float norm2 = red[0];
        for (int l = tid; l < LN; l += 256) {
            float t = step * (float)l;
            float v = 3.f + 2.f * cosf(t) + 2.f * cosf(0.5f * t) + 2.f * cosf(1.5f * t);
            v = fmaxf(v, 0.f);
            g_a[f * LN + l] = sqrtf(v / norm2);
        }
    } else {
        int idx = (blockIdx.x - NF) * 256 + tid;
        if (idx >= LN * DN) return;
        int l = idx / DN, d = idx % DN;
        float t = 2.f * PI_F * (float)l / (float)(LMAXN - 1);
        float pd = 2.f * PI_F * (float)d / (float)DN;
        float sr = 0.f, si = 0.f;
        for (int i = 0; i < 8; i++) {
            float base = 0.1f * (float)i;
#pragma unroll
            for (int a = 0; a < 3; a++) {
                float fr = (0.3f - 0.1f * (float)a) + base;
                float ang = fr * t + pd;
                sr += cosf(ang);
                si += sinf(ang);
            }
        }
        const float C = (1.f / sqrtf((float)LMAXN)) / (sqrtf(3.f) * sqrtf(8.f));
        g_epr[idx] = sr * C;
        g_epi[idx] = si * C;
    }
}

// ---------------- P2b+P3 fused: Q/K bf16 convert  AND  V^T + colsum -------
__global__ __launch_bounds__(256) void convert_kernel(
    const float* __restrict__ Qr, const float* __restrict__ Qi,
    const float* __restrict__ Kr, const float* __restrict__ Ki,
    const float* __restrict__ Vr, const float* __restrict__ Vi) {
    __shared__ float sr[64][65], si[64][65];
    __shared__ float csr4[4][64], csi4[4][64];
    int tile = blockIdx.x, bh = blockIdx.y, arr = blockIdx.z;
    int tid = threadIdx.x;
    if (arr < 4) {
        const float* src = (arr == 0 ? Qr : arr == 1 ? Qi : arr == 2 ? Kr : Ki)
                           + ((size_t)bh * LN + (size_t)tile * 64) * DN;
        char* dst = (char*)(g_qk[arr] + ((size_t)(bh * 16 + tile)) * 4096);
#pragma unroll
        for (int k = 0; k < 4; k++) {
            int i = tid + k * 256;
            int row = i >> 4, c4 = i & 15;
            float4 v = *(const float4*)(src + row * 64 + c4 * 4);
            uint32_t p0, p1;
            asm("cvt.rn.bf16x2.f32 %0, %1, %2;" : "=r"(p0) : "f"(v.y), "f"(v.x));
            asm("cvt.rn.bf16x2.f32 %0, %1, %2;" : "=r"(p1) : "f"(v.w), "f"(v.z));
            uint32_t off = (uint32_t)(row * 128 + c4 * 8);
            off ^= ((uint32_t)(row & 7) << 4);
            *(uint32_t*)(dst + off) = p0;
            *(uint32_t*)(dst + off + 4) = p1;
        }
        return;
    }
    int mt = tile;
    const float* vrb = Vr + ((size_t)bh * LN + (size_t)mt * 64) * DN;
    const float* vib = Vi + ((size_t)bh * LN + (size_t)mt * 64) * DN;
#pragma unroll
    for (int k = 0; k < 16; k++) {
        int i = tid + k * 256;
        int m = i >> 6, d = i & 63;
        sr[m][d] = vrb[i];
        si[m][d] = vib[i];
    }
    __syncthreads();
#pragma unroll
    for (int k = 0; k < 8; k++) {
        int i = tid + k * 256;
        int d = i >> 5, mp = i & 31, m = mp * 2;
        uint32_t pr, pi;
        asm("cvt.rn.bf16x2.f32 %0, %1, %2;" : "=r"(pr) : "f"(sr[m + 1][d]), "f"(sr[m][d]));
        asm("cvt.rn.bf16x2.f32 %0, %1, %2;" : "=r"(pi) : "f"(si[m + 1][d]), "f"(si[m][d]));
        size_t o = (size_t)bh * DN * LN + (size_t)d * LN + mt * 64 + m;
        *(uint32_t*)&g_vtr[o] = pr;
        *(uint32_t*)&g_vti[o] = pi;
    }
    {
        int d = tid & 63, seg = tid >> 6;
        float aR = 0.f, aI = 0.f;
#pragma unroll
        for (int j = 0; j < 16; j++) {
            aR += sr[seg * 16 + j][d];
            aI += si[seg * 16 + j][d];
        }
        csr4[seg][d] = aR; csi4[seg][d] = aI;
    }
    __syncthreads();
    if (tid < 64) {
        int d = tid;
        g_cspr[(mt * BHN + bh) * DN + d] = csr4[0][d] + csr4[1][d] + csr4[2][d] + csr4[3][d];
        g_cspi[(mt * BHN + bh) * DN + d] = csi4[0][d] + csi4[1][d] + csi4[2][d] + csi4[3][d];
    }
}

// ---- 8KB tile prefetch: 2 cp.async.16B per thread (256 thr) ----
__device__ __forceinline__ void prefetch_tile(uint32_t dst, const char* src, int tid) {
#pragma unroll
    for (int i = 0; i < 2; i++) {
        int o = (tid + i * 256) * 16;
        CPASYNC16(dst + o, src + o);
    }
}

// ---------------- A: gram; s1 moment computed ON the tensor core ----------
__global__ __launch_bounds__(256, 2) void gram_mma_kernel() {
    __shared__ __align__(16) uint32_t s_q[2][2048];      // qr, qi tiles
    __shared__ __align__(16) uint32_t s_k[2][2][2048];   // [buf][kr/ki]
    __shared__ float sAm[NF][256];

    int tid = threadIdx.x;
    int lane = tid & 31, w = tid >> 5;
    int wr = w >> 1, wc = w & 1;
    int mtg = blockIdx.x, lt = blockIdx.y, bh = blockIdx.z;

    const char* qrt = (const char*)(g_qk[0] + ((size_t)(bh * 16 + lt)) * 4096);
    const char* qit = (const char*)(g_qk[1] + ((size_t)(bh * 16 + lt)) * 4096);
    const char* krb = (const char*)(g_qk[2] + ((size_t)(bh * 16 + mtg * 4)) * 4096);
    const char* kib = (const char*)(g_qk[3] + ((size_t)(bh * 16 + mtg * 4)) * 4096);

    uint32_t aq0 = smem_u32(s_q[0]), aq1 = smem_u32(s_q[1]);

    prefetch_tile(aq0, qrt, tid);
    prefetch_tile(aq1, qit, tid);
    prefetch_tile(smem_u32(s_k[0][0]), krb, tid);
    prefetch_tile(smem_u32(s_k[0][1]), kib, tid);
    CPCOMMIT();
#pragma unroll
    for (int i = tid; i < NF * 256; i += 256)
        sAm[i >> 8][i & 255] = g_a[(i >> 8) * LN + mtg * 256 + (i & 255)];
    CPWAIT0();
    __syncthreads();

    int l16 = lane & 15, ac = lane >> 4;
    uint32_t aR[4][4], aI[4][4];
#pragma unroll
    for (int ks = 0; ks < 4; ks++) {
        int row = wr * 16 + l16;
        uint32_t off = (uint32_t)(row * 128 + ac * 16 + ks * 32);
        uint32_t sw = off ^ ((uint32_t)(row & 7) << 4);
        LDSM_X4(aR[ks], aq0 + sw);
        LDSM_X4(aI[ks], aq1 + sw);
    }

    int b_row = ((lane >> 4) << 3) + (lane & 7);
    int b_kh = (lane >> 3) & 1;
    int qrow = lane >> 2, qcol = (lane & 3) * 2;
    int fq = qrow;
    bool act = fq < NF;

    float sacc[4] = {0.f, 0.f, 0.f, 0.f};

    for (int it = 0; it < 4; it++) {
        int mt = mtg * 4 + it;
        if (it > 0) CPWAIT0();
        __syncthreads();
        if (it < 3) {
            prefetch_tile(smem_u32(s_k[(it + 1) & 1][0]), krb + (size_t)(it + 1) * 8192, tid);
            prefetch_tile(smem_u32(s_k[(it + 1) & 1][1]), kib + (size_t)(it + 1) * 8192, tid);
            CPCOMMIT();
        }

        uint32_t akr = smem_u32(s_k[it & 1][0]), aki = smem_u32(s_k[it & 1][1]);
        float cr[4][4] = {}, ci[4][4] = {};
#pragma unroll
        for (int ks = 0; ks < 4; ks++) {
            uint32_t bR[8], bI[8], bIn[8];
#pragma unroll
            for (int p = 0; p < 2; p++) {
                int row = wc * 32 + p * 16 + b_row;
                uint32_t off = (uint32_t)(row * 128 + b_kh * 16 + ks * 32);
                uint32_t sw = off ^ ((uint32_t)(row & 7) << 4);
                LDSM_X4(bR + p * 4, akr + sw);
                LDSM_X4(bI + p * 4, aki + sw);
            }
#pragma unroll
            for (int j = 0; j < 8; j++) bIn[j] = bI[j] ^ 0x80008000u;
#pragma unroll
            for (int ni = 0; ni < 4; ni++) {
                MMA16816(cr[ni], aR[ks], (bR + ni * 2));
                MMA16816(cr[ni], aI[ks], (bIn + ni * 2));
                MMA16816(ci[ni], aR[ks], (bI + ni * 2));
                MMA16816(ci[ni], aI[ks], (bR + ni * 2));
            }
        }

        __nv_bfloat16* gb = g_gram + (size_t)bh * LN * LN;
        int r0 = lt * 64 + wr * 16 + qrow;
#pragma unroll
        for (int ks2 = 0; ks2 < 2; ks2++) {
            uint32_t Afrag[4];
#pragma unroll
            for (int nio = 0; nio < 2; nio++) {
                int ni = ks2 * 2 + nio;
                float mg[4];
#pragma unroll
                for (int j = 0; j < 4; j++) {
                    float c = cr[ni][j], d = ci[ni][j];
                    float m2 = c * c + d * d;
                    float s;
                    asm("sqrt.approx.f32 %0, %1;" : "=f"(s) : "f"(m2));
                    mg[j] = s * 0.125f;
                }
                uint32_t p01, p23;
                asm("cvt.rn.bf16x2.f32 %0, %1, %2;" : "=r"(p01) : "f"(mg[1]), "f"(mg[0]));
                asm("cvt.rn.bf16x2.f32 %0, %1, %2;" : "=r"(p23) : "f"(mg[3]), "f"(mg[2]));
                int mcol = mt * 64 + wc * 32 + ni * 8 + qcol;
                *(uint32_t*)(gb + (size_t)r0 * LN + mcol) = p01;
                *(uint32_t*)(gb + (size_t)(r0 + 8) * LN + mcol) = p23;
                Afrag[nio * 2 + 0] = p01;
                Afrag[nio * 2 + 1] = p23;
            }
            int mb = it * 64 + wc * 32 + ks2 * 16;
            float a0 = 0.f, a1 = 0.f, a2 = 0.f, a3 = 0.f;
            if (act) {
                a0 = sAm[fq][mb + qcol];     a1 = sAm[fq][mb + qcol + 1];
                a2 = sAm[fq][mb + qcol + 8]; a3 = sAm[fq][mb + qcol + 9];
            }
            uint32_t Bfrag[2];
            asm("cvt.rn.bf16x2.f32 %0, %1, %2;" : "=r"(Bfrag[0]) : "f"(a1), "f"(a0));
            asm("cvt.rn.bf16x2.f32 %0, %1, %2;" : "=r"(Bfrag[1]) : "f"(a3), "f"(a2));
            MMA16816(sacc, Afrag, Bfrag);
        }
    }

    if ((lane & 3) < 2) {
        int slot = mtg * 2 + wc;
        int r0 = lt * 64 + wr * 16 + qrow;
        size_t base = (size_t)slot * PARTN + (size_t)bh * NF * LN;
        g_p1[base + (size_t)qcol * LN + r0] = sacc[0];
        g_p1[base + (size_t)(qcol + 1) * LN + r0] = sacc[1];
        g_p1[base + (size_t)qcol * LN + r0 + 8] = sacc[2];
        g_p1[base + (size_t)(qcol + 1) * LN + r0 + 8] = sacc[3];
    }
}

// ---- Vt tile prefetch (64 rows, swizzled; 256 thr) ----
__device__ __forceinline__ void prefetch_vt64(
    uint32_t dr, uint32_t di,
    const __nv_bfloat16* vtr, const __nv_bfloat16* vti, int mt, int tid) {
#pragma unroll
    for (int k = 0; k < 2; k++) {
        int i = tid + k * 256;           // 0..511
        int row = i >> 3, c16 = i & 7;
        uint32_t off = (uint32_t)(row * 128 + c16 * 16);
        uint32_t sw = off ^ ((uint32_t)(row & 7) << 4);
        CPASYNC16(dr + sw, (const char*)(vtr + (size_t)row * LN + mt * 64) + c16 * 16);
        CPASYNC16(di + sw, (const char*)(vti + (size_t)row * LN + mt * 64) + c16 * 16);
    }
}

// ---- g tile prefetch: 64 rows x 128B, plain layout (256 thr) ----
__device__ __forceinline__ void prefetch_g64(
    uint32_t dst, const __nv_bfloat16* gb, int mt, int tid) {
#pragma unroll
    for (int k = 0; k < 2; k++) {
        int i = tid + k * 256;           // 0..511
        int row = i >> 3, c16 = i & 7;
        CPASYNC16(dst + (uint32_t)(row * 128 + c16 * 16),
                  (const char*)(gb + (size_t)row * LN + mt * 64) + c16 * 16);
    }
}

// ---------------- C: 256 thr, 64 l-rows (gram's shape), g+Vt prefetched ----
__global__ __launch_bounds__(256, 2) void attn_mma_kernel(float* __restrict__ out) {
    __shared__ __align__(16) uint32_t s_w[2048];        // dW bf16 64x64 swizzled
    __shared__ __align__(16) uint32_t s_vr[2][2048];
    __shared__ __align__(16) uint32_t s_vi[2][2048];
    __shared__ __align__(16) uint32_t s_g[2][2048];     // g tiles 64x64 bf16 plain
    __shared__ float s_c[NF][64];
    __shared__ float s_base[64];
    __shared__ float s_csr[64], s_csi[64];
    __shared__ float s_is[NF][64];

    int tid = threadIdx.x;
    int lane = tid & 31, w = tid >> 5;
    int wr = w >> 1, wc = w & 1;                // 4 row bands x 2 d halves
    int lt = blockIdx.x, bh = blockIdx.y;       // 16 x 32 = 512 blocks

    uint32_t a_w = smem_u32(s_w);
    const __nv_bfloat16* vtr = g_vtr + (size_t)bh * DN * LN;
    const __nv_bfloat16* vti = g_vti + (size_t)bh * DN * LN;
    const __nv_bfloat16* gb = g_gram + (size_t)bh * LN * LN + (size_t)lt * 64 * LN;

    // prologue prefetch: g[0] + Vt[0]
    prefetch_g64(smem_u32(s_g[0]), gb, 0, tid);
    prefetch_vt64(smem_u32(s_vr[0]), smem_u32(s_vi[0]), vtr, vti, 0, tid);
    CPCOMMIT();

    // invS reduction: one (f, r) per thread
    {
        int f = tid >> 6, r = tid & 63;
        int lg = lt * 64 + r;
        const float* p = g_p1 + ((size_t)bh * NF + f) * LN + lg;
        float s1 = 0.f;
#pragma unroll
        for (int i = 0; i < 8; i++) s1 += p[(size_t)i * PARTN];
        float al = g_a[f * LN + lg];
        s_is[f][r] = 1.f / (1024.f + al * s1);
    }
    __syncthreads();
    if (tid < 64) {
        int lg = lt * 64 + tid;
        float b = 0.f;
#pragma unroll
        for (int f = 0; f < NF; f++) {
            float is = s_is[f][tid];
            s_c[f][tid] = is * g_a[f * LN + lg];
            b += is;
        }
        s_base[tid] = b;
    }
    if (tid >= 64 && tid < 128) {
        int d = tid - 64;
        float csR = 0.f, csI = 0.f;
#pragma unroll
        for (int m2 = 0; m2 < 16; m2++) {
            csR += g_cspr[(m2 * BHN + bh) * DN + d];
            csI += g_cspi[(m2 * BHN + bh) * DN + d];
        }
        s_csr[d] = csR;
        s_csi[d] = csI;
    }

    float accr[4][4] = {}, acci[4][4] = {};

    int l16 = lane & 15, ac = lane >> 4;
    int bm0 = (tid & 31) * 2, lgrp = tid >> 5;  // 8 groups x 8 rows = 64
    int b_row = ((lane >> 4) << 3) + (lane & 7);
    int b_kh = (lane >> 3) & 1;

    for (int mt = 0; mt < 16; mt++) {
        __syncthreads();          // prior iteration's buffer reads done
        if (mt < 15) {
            prefetch_g64(smem_u32(s_g[(mt + 1) & 1]), gb, mt + 1, tid);
            prefetch_vt64(smem_u32(s_vr[(mt + 1) & 1]), smem_u32(s_vi[(mt + 1) & 1]),
                          vtr, vti, mt + 1, tid);
            CPCOMMIT();
            CPWAIT1();            // group(mt) complete
        } else {
            CPWAIT0();
        }
        __syncthreads();          // group(mt) data visible
        // ---- build dW tile from smem g: 8 rows per thread ----
        {
            uint32_t sg = smem_u32(s_g[mt & 1]);
            float am0[NF], am1[NF];
#pragma unroll
            for (int f = 0; f < NF; f++) {
                am0[f] = g_a[f * LN + mt * 64 + bm0];
                am1[f] = g_a[f * LN + mt * 64 + bm0 + 1];
            }
#pragma unroll 4
            for (int li = 0; li < 8; li++) {
                int l = lgrp * 8 + li;
                float dot0 = 0.f, dot1 = 0.f;
#pragma unroll
                for (int f = 0; f < NF; f++) {
                    float c = s_c[f][l];
                    dot0 = fmaf(c, am0[f], dot0);
                    dot1 = fmaf(c, am1[f], dot1);
                }
                uint32_t gp;
                asm volatile("ld.shared.b32 %0, [%1];"
                             : "=r"(gp) : "r"(sg + (uint32_t)(l * 128 + bm0 * 2)));
                float2 gf = __bfloat1622float2(*(__nv_bfloat162*)&gp);
                float w0 = dot0 * gf.x;
                float w1 = dot1 * gf.y;
                uint32_t p;
                asm("cvt.rn.bf16x2.f32 %0, %1, %2;" : "=r"(p) : "f"(w1), "f"(w0));
                uint32_t off = (uint32_t)(l * 128 + bm0 * 2);
                uint32_t sw = off ^ ((uint32_t)(l & 7) << 4);
                sts32(a_w + sw, p);
            }
        }
        __syncthreads();          // s_w ready
        uint32_t avr = smem_u32(s_vr[mt & 1]), avi = smem_u32(s_vi[mt & 1]);
#pragma unroll
        for (int ks = 0; ks < 4; ks++) {
            uint32_t aW[4];
            {
                int row = wr * 16 + l16;
                uint32_t off = (uint32_t)(row * 128 + ac * 16 + ks * 32);
                uint32_t sw = off ^ ((uint32_t)(row & 7) << 4);
                LDSM_X4(aW, a_w + sw);
            }
            uint32_t bR[8], bI[8];
#pragma unroll
            for (int p = 0; p < 2; p++) {
                int row = wc * 32 + p * 16 + b_row;
                uint32_t off = (uint32_t)(row * 128 + b_kh * 16 + ks * 32);
                uint32_t sw = off ^ ((uint32_t)(row & 7) << 4);
                LDSM_X4(bR + p * 4, avr + sw);
                LDSM_X4(bI + p * 4, avi + sw);
            }
#pragma unroll
            for (int ni = 0; ni < 4; ni++) {
                MMA16816(accr[ni], aW, (bR + ni * 2));
                MMA16816(acci[ni], aW, (bI + ni * 2));
            }
        }
    }

    int qrow = lane >> 2, qcol = (lane & 3) * 2;
    const size_t imag_off = (size_t)BHN * LN * DN;
    float* ob = out + (size_t)bh * LN * DN;
#pragma unroll
    for (int half = 0; half < 2; half++) {
        int lrow = wr * 16 + half * 8 + qrow;
        int lg = lt * 64 + lrow;
        float base = s_base[lrow];
#pragma unroll
        for (int ni = 0; ni < 4; ni++) {
            int d = wc * 32 + ni * 8 + qcol;
            float ar0 = fmaf(base, s_csr[d], accr[ni][half * 2]) * 0.5f;
            float ai0 = fmaf(base, s_csi[d], acci[ni][half * 2]) * 0.5f;
            float ar1 = fmaf(base, s_csr[d + 1], accr[ni][half * 2 + 1]) * 0.5f;
            float ai1 = fmaf(base, s_csi[d + 1], acci[ni][half * 2 + 1]) * 0.5f;
            float2 er = *(const float2*)(g_epr + lg * DN + d);
            float2 ei = *(const float2*)(g_epi + lg * DN + d);
            float2 oR, oI;
            oR.x = ar0 * er.x - ai0 * ei.x;
            oI.x = ar0 * ei.x + ai0 * er.x;
            oR.y = ar1 * er.y - ai1 * ei.y;
            oI.y = ar1 * ei.y + ai1 * er.y;
            *(float2*)(ob + (size_t)lg * DN + d) = oR;
            *(float2*)(ob + imag_off + (size_t)lg * DN + d) = oI;
        }
    }
}

// ---------------- launcher ----------------
extern "C" void kernel_launch(void* const* d_in, const int* in_sizes, int n_in,
                              void* d_out, int out_size) {
    (void)in_sizes; (void)n_in; (void)out_size;
    const float* Qr = (const float*)d_in[0];
    const float* Qi = (const float*)d_in[1];
    const float* Kr = (const float*)d_in[2];
    const float* Ki = (const float*)d_in[3];
    const float* Vr = (const float*)d_in[4];
    const float* Vi = (const float*)d_in[5];
    float* out = (float*)d_out;

    prep_kernel<<<NF + (LN * DN + 255) / 256, 256>>>();
    convert_kernel<<<dim3(16, BHN, 5), 256>>>(Qr, Qi, Kr, Ki, Vr, Vi);
    gram_mma_kernel<<<dim3(4, 16, BHN), 256>>>();
    attn_mma_kernel<<<dim3(16, BHN), 256>>>(out);
}

// round 14
// speedup vs baseline: 1.2304x; 1.1080x over previous
#include <cuda_runtime.h>
#include <cuda_bf16.h>
#include <stdint.h>
#include <math.h>

#define BHN 32          // B*H
#define LN 1024
#define DN 64
#define LMAXN 2048
#define NF 4
#define PARTN (BHN * NF * LN)   // 131072
#define PI_F 3.14159265358979323846f

// ---------------- device scratch (static allocation only) ----------------
__device__ __nv_bfloat16 g_gram[(size_t)BHN * LN * LN];  // 64 MB
__device__ __nv_bfloat16 g_qk[4][(size_t)BHN * 16 * 4096]; // bf16 swizzled tiles qr,qi,kr,ki
__device__ float g_a[NF * LN];
__device__ float g_p1[(size_t)8 * PARTN];             // s1 partials, slot-major (8 slots)
__device__ float g_epr[LN * DN];
__device__ float g_epi[LN * DN];
__device__ __nv_bfloat16 g_vtr[(size_t)BHN * DN * LN];
__device__ __nv_bfloat16 g_vti[(size_t)BHN * DN * LN];
__device__ float g_cspr[16 * BHN * DN];
__device__ float g_cspi[16 * BHN * DN];

__device__ __forceinline__ uint32_t smem_u32(const void* p) {
    uint32_t a;
    asm("{ .reg .u64 t; cvta.to.shared.u64 t, %1; cvt.u32.u64 %0, t; }" : "=r"(a) : "l"(p));
    return a;
}
__device__ __forceinline__ void sts32(uint32_t a, uint32_t v) {
    asm volatile("st.shared.b32 [%0], %1;" :: "r"(a), "r"(v));
}

#define LDSM_X4(r, a) \
    asm volatile("ldmatrix.sync.aligned.m8n8.x4.shared.b16 {%0,%1,%2,%3}, [%4];" \
        : "=r"((r)[0]), "=r"((r)[1]), "=r"((r)[2]), "=r"((r)[3]) : "r"(a))
#define MMA16816(d, a, b) \
    asm volatile("mma.sync.aligned.m16n8k16.row.col.f32.bf16.bf16.f32 " \
        "{%0,%1,%2,%3},{%4,%5,%6,%7},{%8,%9},{%0,%1,%2,%3};" \
        : "+f"((d)[0]), "+f"((d)[1]), "+f"((d)[2]), "+f"((d)[3]) \
        : "r"((a)[0]), "r"((a)[1]), "r"((a)[2]), "r"((a)[3]), "r"((b)[0]), "r"((b)[1]))
#define CPASYNC16(dst, src) \
    asm volatile("cp.async.cg.shared.global [%0], [%1], 16;" :: "r"(dst), "l"(src))
#define CPCOMMIT() asm volatile("cp.async.commit_group;" ::: "memory")
#define CPWAIT0()  asm volatile("cp.async.wait_group 0;" ::: "memory")
#define CPWAIT1()  asm volatile("cp.async.wait_group 1;" ::: "memory")

// ------- fused convert: Q/K bf16 tiles, V^T + colsum, AND prep (z=5) -------
__global__ __launch_bounds__(256) void convert_kernel(
    const float* __restrict__ Qr, const float* __restrict__ Qi,
    const float* __restrict__ Kr, const float* __restrict__ Ki,
    const float* __restrict__ Vr, const float* __restrict__ Vi) {
    __shared__ float sr[64][65], si[64][65];
    __shared__ float csr4[4][64], csi4[4][64];
    __shared__ float red[256];
    int tile = blockIdx.x, bh = blockIdx.y, arr = blockIdx.z;
    int tid = threadIdx.x;
    if (arr < 4) {
        // fp32 -> swizzled bf16 tiles for Q/K
        const float* src = (arr == 0 ? Qr : arr == 1 ? Qi : arr == 2 ? Kr : Ki)
                           + ((size_t)bh * LN + (size_t)tile * 64) * DN;
        char* dst = (char*)(g_qk[arr] + ((size_t)(bh * 16 + tile)) * 4096);
#pragma unroll
        for (int k = 0; k < 4; k++) {
            int i = tid + k * 256;
            int row = i >> 4, c4 = i & 15;
            float4 v = *(const float4*)(src + row * 64 + c4 * 4);
            uint32_t p0, p1;
            asm("cvt.rn.bf16x2.f32 %0, %1, %2;" : "=r"(p0) : "f"(v.y), "f"(v.x));
            asm("cvt.rn.bf16x2.f32 %0, %1, %2;" : "=r"(p1) : "f"(v.w), "f"(v.z));
            uint32_t off = (uint32_t)(row * 128 + c4 * 8);
            off ^= ((uint32_t)(row & 7) << 4);
            *(uint32_t*)(dst + off) = p0;
            *(uint32_t*)(dst + off + 4) = p1;
        }
        return;
    }
    if (arr == 5) {
        // ---- prep slice: expert pattern spread over all 512 (tile,bh) blocks ----
        int blk = bh * 16 + tile;            // 0..511
        {
            int idx = blk * 128 + (tid & 127);   // two threads per elem? no: 128 elems, tid<128
            if (tid < 128) {
                int l = idx / DN, d = idx % DN;
                float t = 2.f * PI_F * (float)l / (float)(LMAXN - 1);
                float pd = 2.f * PI_F * (float)d / (float)DN;
                float srv = 0.f, siv = 0.f;
                for (int i = 0; i < 8; i++) {
                    float base = 0.1f * (float)i;
#pragma unroll
                    for (int a = 0; a < 3; a++) {
                        float fr = (0.3f - 0.1f * (float)a) + base;
                        float ang = fr * t + pd;
                        srv += cosf(ang);
                        siv += sinf(ang);
                    }
                }
                const float C = (1.f / sqrtf((float)LMAXN)) / (sqrtf(3.f) * sqrtf(8.f));
                g_epr[idx] = srv * C;
                g_epi[idx] = siv * C;
            }
        }
        // freq-pattern blocks: tile<4, bh==0 (block-wide reduction)
        if (bh == 0 && tile < NF) {
            const float freqs[NF] = {1.0f, 0.5f, 0.25f, 0.1f};
            int f = tile;
            float step = 2.f * PI_F * freqs[f] / (float)(LMAXN - 1);
            float s = 0.f;
            for (int j = tid; j < LMAXN; j += 256) {
                float t = step * (float)j;
                s += 3.f + 2.f * cosf(t) + 2.f * cosf(0.5f * t) + 2.f * cosf(1.5f * t);
            }
            red[tid] = s;
            __syncthreads();
            for (int o = 128; o > 0; o >>= 1) {
                if (tid < o) red[tid] += red[tid + o];
                __syncthreads();
            }
            float norm2 = red[0];
            for (int l = tid; l < LN; l += 256) {
                float t = step * (float)l;
                float v = 3.f + 2.f * cosf(t) + 2.f * cosf(0.5f * t) + 2.f * cosf(1.5f * t);
                v = fmaxf(v, 0.f);
                g_a[f * LN + l] = sqrtf(v / norm2);
            }
        }
        return;
    }
    // arr == 4: V^T bf16 precompute + colsum partials
    int mt = tile;
    const float* vrb = Vr + ((size_t)bh * LN + (size_t)mt * 64) * DN;
    const float* vib = Vi + ((size_t)bh * LN + (size_t)mt * 64) * DN;
#pragma unroll
    for (int k = 0; k < 16; k++) {
        int i = tid + k * 256;
        int m = i >> 6, d = i & 63;
        sr[m][d] = vrb[i];
        si[m][d] = vib[i];
    }
    __syncthreads();
#pragma unroll
    for (int k = 0; k < 8; k++) {
        int i = tid + k * 256;
        int d = i >> 5, mp = i & 31, m = mp * 2;
        uint32_t pr, pi;
        asm("cvt.rn.bf16x2.f32 %0, %1, %2;" : "=r"(pr) : "f"(sr[m + 1][d]), "f"(sr[m][d]));
        asm("cvt.rn.bf16x2.f32 %0, %1, %2;" : "=r"(pi) : "f"(si[m + 1][d]), "f"(si[m][d]));
        size_t o = (size_t)bh * DN * LN + (size_t)d * LN + mt * 64 + m;
        *(uint32_t*)&g_vtr[o] = pr;
        *(uint32_t*)&g_vti[o] = pi;
    }
    {
        int d = tid & 63, seg = tid >> 6;
        float aR = 0.f, aI = 0.f;
#pragma unroll
        for (int j = 0; j < 16; j++) {
            aR += sr[seg * 16 + j][d];
            aI += si[seg * 16 + j][d];
        }
        csr4[seg][d] = aR; csi4[seg][d] = aI;
    }
    __syncthreads();
    if (tid < 64) {
        int d = tid;
        g_cspr[(mt * BHN + bh) * DN + d] = csr4[0][d] + csr4[1][d] + csr4[2][d] + csr4[3][d];
        g_cspi[(mt * BHN + bh) * DN + d] = csi4[0][d] + csi4[1][d] + csi4[2][d] + csi4[3][d];
    }
}

// ---- 8KB tile prefetch: 2 cp.async.16B per thread (256 thr) ----
__device__ __forceinline__ void prefetch_tile(uint32_t dst, const char* src, int tid) {
#pragma unroll
    for (int i = 0; i < 2; i++) {
        int o = (tid + i * 256) * 16;
        CPASYNC16(dst + o, src + o);
    }
}

// ---------------- A: gram; s1 moment computed ON the tensor core ----------
__global__ __launch_bounds__(256, 2) void gram_mma_kernel() {
    __shared__ __align__(16) uint32_t s_q[2][2048];      // qr, qi tiles
    __shared__ __align__(16) uint32_t s_k[2][2][2048];   // [buf][kr/ki]
    __shared__ float sAm[NF][256];

    int tid = threadIdx.x;
    int lane = tid & 31, w = tid >> 5;
    int wr = w >> 1, wc = w & 1;
    int mtg = blockIdx.x, lt = blockIdx.y, bh = blockIdx.z;

    const char* qrt = (const char*)(g_qk[0] + ((size_t)(bh * 16 + lt)) * 4096);
    const char* qit = (const char*)(g_qk[1] + ((size_t)(bh * 16 + lt)) * 4096);
    const char* krb = (const char*)(g_qk[2] + ((size_t)(bh * 16 + mtg * 4)) * 4096);
    const char* kib = (const char*)(g_qk[3] + ((size_t)(bh * 16 + mtg * 4)) * 4096);

    uint32_t aq0 = smem_u32(s_q[0]), aq1 = smem_u32(s_q[1]);

    prefetch_tile(aq0, qrt, tid);
    prefetch_tile(aq1, qit, tid);
    prefetch_tile(smem_u32(s_k[0][0]), krb, tid);
    prefetch_tile(smem_u32(s_k[0][1]), kib, tid);
    CPCOMMIT();
#pragma unroll
    for (int i = tid; i < NF * 256; i += 256)
        sAm[i >> 8][i & 255] = g_a[(i >> 8) * LN + mtg * 256 + (i & 255)];
    CPWAIT0();
    __syncthreads();

    int l16 = lane & 15, ac = lane >> 4;
    uint32_t aR[4][4], aI[4][4];
#pragma unroll
    for (int ks = 0; ks < 4; ks++) {
        int row = wr * 16 + l16;
        uint32_t off = (uint32_t)(row * 128 + ac * 16 + ks * 32);
        uint32_t sw = off ^ ((uint32_t)(row & 7) << 4);
        LDSM_X4(aR[ks], aq0 + sw);
        LDSM_X4(aI[ks], aq1 + sw);
    }

    int b_row = ((lane >> 4) << 3) + (lane & 7);
    int b_kh = (lane >> 3) & 1;
    int qrow = lane >> 2, qcol = (lane & 3) * 2;
    int fq = qrow;
    bool act = fq < NF;

    float sacc[4] = {0.f, 0.f, 0.f, 0.f};

    for (int it = 0; it < 4; it++) {
        int mt = mtg * 4 + it;
        if (it > 0) CPWAIT0();
        __syncthreads();
        if (it < 3) {
            prefetch_tile(smem_u32(s_k[(it + 1) & 1][0]), krb + (size_t)(it + 1) * 8192, tid);
            prefetch_tile(smem_u32(s_k[(it + 1) & 1][1]), kib + (size_t)(it + 1) * 8192, tid);
            CPCOMMIT();
        }

        uint32_t akr = smem_u32(s_k[it & 1][0]), aki = smem_u32(s_k[it & 1][1]);
        float cr[4][4] = {}, ci[4][4] = {};
#pragma unroll
        for (int ks = 0; ks < 4; ks++) {
            uint32_t bR[8], bI[8], bIn[8];
#pragma unroll
            for (int p = 0; p < 2; p++) {
                int row = wc * 32 + p * 16 + b_row;
                uint32_t off = (uint32_t)(row * 128 + b_kh * 16 + ks * 32);
                uint32_t sw = off ^ ((uint32_t)(row & 7) << 4);
                LDSM_X4(bR + p * 4, akr + sw);
                LDSM_X4(bI + p * 4, aki + sw);
            }
#pragma unroll
            for (int j = 0; j < 8; j++) bIn[j] = bI[j] ^ 0x80008000u;
#pragma unroll
            for (int ni = 0; ni < 4; ni++) {
                MMA16816(cr[ni], aR[ks], (bR + ni * 2));
                MMA16816(cr[ni], aI[ks], (bIn + ni * 2));
                MMA16816(ci[ni], aR[ks], (bI + ni * 2));
                MMA16816(ci[ni], aI[ks], (bR + ni * 2));
            }
        }

        __nv_bfloat16* gb = g_gram + (size_t)bh * LN * LN;
        int r0 = lt * 64 + wr * 16 + qrow;
#pragma unroll
        for (int ks2 = 0; ks2 < 2; ks2++) {
            uint32_t Afrag[4];
#pragma unroll
            for (int nio = 0; nio < 2; nio++) {
                int ni = ks2 * 2 + nio;
                float mg[4];
#pragma unroll
                for (int j = 0; j < 4; j++) {
                    float c = cr[ni][j], d = ci[ni][j];
                    float m2 = c * c + d * d;
                    float s;
                    asm("sqrt.approx.f32 %0, %1;" : "=f"(s) : "f"(m2));
                    mg[j] = s * 0.125f;
                }
                uint32_t p01, p23;
                asm("cvt.rn.bf16x2.f32 %0, %1, %2;" : "=r"(p01) : "f"(mg[1]), "f"(mg[0]));
                asm("cvt.rn.bf16x2.f32 %0, %1, %2;" : "=r"(p23) : "f"(mg[3]), "f"(mg[2]));
                int mcol = mt * 64 + wc * 32 + ni * 8 + qcol;
                *(uint32_t*)(gb + (size_t)r0 * LN + mcol) = p01;
                *(uint32_t*)(gb + (size_t)(r0 + 8) * LN + mcol) = p23;
                Afrag[nio * 2 + 0] = p01;
                Afrag[nio * 2 + 1] = p23;
            }
            int mb = it * 64 + wc * 32 + ks2 * 16;
            float a0 = 0.f, a1 = 0.f, a2 = 0.f, a3 = 0.f;
            if (act) {
                a0 = sAm[fq][mb + qcol];     a1 = sAm[fq][mb + qcol + 1];
                a2 = sAm[fq][mb + qcol + 8]; a3 = sAm[fq][mb + qcol + 9];
            }
            uint32_t Bfrag[2];
            asm("cvt.rn.bf16x2.f32 %0, %1, %2;" : "=r"(Bfrag[0]) : "f"(a1), "f"(a0));
            asm("cvt.rn.bf16x2.f32 %0, %1, %2;" : "=r"(Bfrag[1]) : "f"(a3), "f"(a2));
            MMA16816(sacc, Afrag, Bfrag);
        }
    }

    if ((lane & 3) < 2) {
        int slot = mtg * 2 + wc;
        int r0 = lt * 64 + wr * 16 + qrow;
        size_t base = (size_t)slot * PARTN + (size_t)bh * NF * LN;
        g_p1[base + (size_t)qcol * LN + r0] = sacc[0];
        g_p1[base + (size_t)(qcol + 1) * LN + r0] = sacc[1];
        g_p1[base + (size_t)qcol * LN + r0 + 8] = sacc[2];
        g_p1[base + (size_t)(qcol + 1) * LN + r0 + 8] = sacc[3];
    }
}

// ---- Vt tile prefetch (64 d-rows, swizzled; 256 thr) ----
__device__ __forceinline__ void prefetch_vt(
    uint32_t dr, uint32_t di,
    const __nv_bfloat16* vtr, const __nv_bfloat16* vti, int mt, int tid) {
#pragma unroll
    for (int k = 0; k < 2; k++) {
        int i = tid + k * 256;           // 0..511
        int row = i >> 3, c16 = i & 7;
        uint32_t off = (uint32_t)(row * 128 + c16 * 16);
        uint32_t sw = off ^ ((uint32_t)(row & 7) << 4);
        CPASYNC16(dr + sw, (const char*)(vtr + (size_t)row * LN + mt * 64) + c16 * 16);
        CPASYNC16(di + sw, (const char*)(vti + (size_t)row * LN + mt * 64) + c16 * 16);
    }
}

// ---- g tile prefetch: 128 rows x 128B, plain layout (256 thr) ----
__device__ __forceinline__ void prefetch_g(
    uint32_t dst, const __nv_bfloat16* gb, int mt, int tid) {
#pragma unroll
    for (int k = 0; k < 4; k++) {
        int i = tid + k * 256;           // 0..1023
        int row = i >> 3, c16 = i & 7;
        CPASYNC16(dst + (uint32_t)(row * 128 + c16 * 16),
                  (const char*)(gb + (size_t)row * LN + mt * 64) + c16 * 16);
    }
}

// -------- C: 256 thr, 128 l-rows, g + Vt cp.async double-buffered (R11) ----
__global__ __launch_bounds__(256, 2) void attn_mma_kernel(float* __restrict__ out) {
    __shared__ __align__(16) uint32_t s_w[4096];        // dW bf16 128x64 swizzled
    __shared__ __align__(16) uint32_t s_vr[2][2048];
    __shared__ __align__(16) uint32_t s_vi[2][2048];
    __shared__ __align__(16) uint32_t s_g[2][4096];     // g tiles 128x64 bf16 plain
    __shared__ float s_c[NF][128];
    __shared__ float s_base[128];
    __shared__ float s_csr[64], s_csi[64];
    __shared__ float s_is[NF][128];

    int tid = threadIdx.x;
    int lane = tid & 31, w = tid >> 5;
    int wr = w >> 1, wc = w & 1;
    int lt2 = blockIdx.x, bh = blockIdx.y;

    uint32_t a_w = smem_u32(s_w);
    const __nv_bfloat16* vtr = g_vtr + (size_t)bh * DN * LN;
    const __nv_bfloat16* vti = g_vti + (size_t)bh * DN * LN;
    const __nv_bfloat16* gb = g_gram + (size_t)bh * LN * LN + (size_t)lt2 * 128 * LN;

    // prologue prefetch: g[0] + Vt[0]
    prefetch_g(smem_u32(s_g[0]), gb, 0, tid);
    prefetch_vt(smem_u32(s_vr[0]), smem_u32(s_vi[0]), vtr, vti, 0, tid);
    CPCOMMIT();

    // invS reduction
#pragma unroll
    for (int idx = tid; idx < NF * 128; idx += 256) {
        int f = idx >> 7, r = idx & 127;
        int lg = lt2 * 128 + r;
        const float* p = g_p1 + ((size_t)bh * NF + f) * LN + lg;
        float s1 = 0.f;
#pragma unroll
        for (int i = 0; i < 8; i++) s1 += p[(size_t)i * PARTN];
        float al = g_a[f * LN + lg];
        s_is[f][r] = 1.f / (1024.f + al * s1);
    }
    __syncthreads();
    if (tid < 128) {
        int lg = lt2 * 128 + tid;
        float b = 0.f;
#pragma unroll
        for (int f = 0; f < NF; f++) {
            float is = s_is[f][tid];
            s_c[f][tid] = is * g_a[f * LN + lg];
            b += is;
        }
        s_base[tid] = b;
    }
    if (tid >= 128 && tid < 192) {
        int d = tid - 128;
        float csR = 0.f, csI = 0.f;
#pragma unroll
        for (int m2 = 0; m2 < 16; m2++) {
            csR += g_cspr[(m2 * BHN + bh) * DN + d];
            csI += g_cspi[(m2 * BHN + bh) * DN + d];
        }
        s_csr[d] = csR;
        s_csi[d] = csI;
    }

    float accr[2][4][4] = {}, acci[2][4][4] = {};

    int l16 = lane & 15, ac = lane >> 4;
    int bm0 = (tid & 31) * 2, lgrp = tid >> 5;
    int b_nii = (lane >> 4) & 1, b_kh = (lane >> 3) & 1, b_l8 = lane & 7;

    for (int mt = 0; mt < 16; mt++) {
        __syncthreads();          // prior iteration's buffer reads done
        if (mt < 15) {
            prefetch_g(smem_u32(s_g[(mt + 1) & 1]), gb, mt + 1, tid);
            prefetch_vt(smem_u32(s_vr[(mt + 1) & 1]), smem_u32(s_vi[(mt + 1) & 1]),
                        vtr, vti, mt + 1, tid);
            CPCOMMIT();
            CPWAIT1();            // group(mt) complete
        } else {
            CPWAIT0();
        }
        __syncthreads();          // group(mt) data visible to all
        // ---- build dW tile from smem g ----
        {
            uint32_t sg = smem_u32(s_g[mt & 1]);
            float am0[NF], am1[NF];
#pragma unroll
            for (int f = 0; f < NF; f++) {
                am0[f] = g_a[f * LN + mt * 64 + bm0];
                am1[f] = g_a[f * LN + mt * 64 + bm0 + 1];
            }
#pragma unroll 4
            for (int li = 0; li < 16; li++) {
                int l = lgrp * 16 + li;
                float dot0 = 0.f, dot1 = 0.f;
#pragma unroll
                for (int f = 0; f < NF; f++) {
                    float c = s_c[f][l];
                    dot0 = fmaf(c, am0[f], dot0);
                    dot1 = fmaf(c, am1[f], dot1);
                }
                uint32_t gp;
                asm volatile("ld.shared.b32 %0, [%1];"
                             : "=r"(gp) : "r"(sg + (uint32_t)(l * 128 + bm0 * 2)));
                float2 gf = __bfloat1622float2(*(__nv_bfloat162*)&gp);
                float w0 = dot0 * gf.x;
                float w1 = dot1 * gf.y;
                uint32_t p;
                asm("cvt.rn.bf16x2.f32 %0, %1, %2;" : "=r"(p) : "f"(w1), "f"(w0));
                uint32_t off = (uint32_t)(l * 128 + bm0 * 2);
                uint32_t sw = off ^ ((uint32_t)(l & 7) << 4);
                sts32(a_w + sw, p);
            }
        }
        __syncthreads();          // s_w ready
        uint32_t avr = smem_u32(s_vr[mt & 1]), avi = smem_u32(s_vi[mt & 1]);
#pragma unroll
        for (int ks = 0; ks < 4; ks++) {
            uint32_t aW[2][4];
#pragma unroll
            for (int mi = 0; mi < 2; mi++) {
                int row = wr * 32 + mi * 16 + l16;
                uint32_t off = (uint32_t)(row * 128 + ac * 16 + ks * 32);
                uint32_t sw = off ^ ((uint32_t)(row & 7) << 4);
                LDSM_X4(aW[mi], a_w + sw);
            }
#pragma unroll
            for (int ni2 = 0; ni2 < 2; ni2++) {
                uint32_t bR[4], bI[4];
                int row = wc * 32 + ni2 * 16 + b_nii * 8 + b_l8;
                uint32_t off = (uint32_t)(row * 128 + b_kh * 16 + ks * 32);
                uint32_t sw = off ^ ((uint32_t)(row & 7) << 4);
                LDSM_X4(bR, avr + sw);
                LDSM_X4(bI, avi + sw);
#pragma unroll
                for (int mi = 0; mi < 2; mi++) {
#pragma unroll
                    for (int h = 0; h < 2; h++) {
                        int ni = ni2 * 2 + h;
                        MMA16816(accr[mi][ni], aW[mi], (bR + h * 2));
                        MMA16816(acci[mi][ni], aW[mi], (bI + h * 2));
                    }
                }
            }
        }
    }

    int qrow = lane >> 2, qcol = (lane & 3) * 2;
    const size_t imag_off = (size_t)BHN * LN * DN;
    float* ob = out + (size_t)bh * LN * DN;
#pragma unroll
    for (int mi = 0; mi < 2; mi++) {
#pragma unroll
        for (int half = 0; half < 2; half++) {
            int lrow = wr * 32 + mi * 16 + half * 8 + qrow;
            int lg = lt2 * 128 + lrow;
            float base = s_base[lrow];
#pragma unroll
            for (int ni = 0; ni < 4; ni++) {
                int d = wc * 32 + ni * 8 + qcol;
                float ar0 = fmaf(base, s_csr[d], accr[mi][ni][half * 2]) * 0.5f;
                float ai0 = fmaf(base, s_csi[d], acci[mi][ni][half * 2]) * 0.5f;
                float ar1 = fmaf(base, s_csr[d + 1], accr[mi][ni][half * 2 + 1]) * 0.5f;
                float ai1 = fmaf(base, s_csi[d + 1], acci[mi][ni][half * 2 + 1]) * 0.5f;
                float2 er = *(const float2*)(g_epr + lg * DN + d);
                float2 ei = *(const float2*)(g_epi + lg * DN + d);
                float2 oR, oI;
                oR.x = ar0 * er.x - ai0 * ei.x;
                oI.x = ar0 * ei.x + ai0 * er.x;
                oR.y = ar1 * er.y - ai1 * ei.y;
                oI.y = ar1 * ei.y + ai1 * er.y;
                *(float2*)(ob + (size_t)lg * DN + d) = oR;
                *(float2*)(ob + imag_off + (size_t)lg * DN + d) = oI;
            }
        }
    }
}

// ---------------- launcher ----------------
extern "C" void kernel_launch(void* const* d_in, const int* in_sizes, int n_in,
                              void* d_out, int out_size) {
    (void)in_sizes; (void)n_in; (void)out_size;
    const float* Qr = (const float*)d_in[0];
    const float* Qi = (const float*)d_in[1];
    const float* Kr = (const float*)d_in[2];
    const float* Ki = (const float*)d_in[3];
    const float* Vr = (const float*)d_in[4];
    const float* Vi = (const float*)d_in[5];
    float* out = (float*)d_out;

    convert_kernel<<<dim3(16, BHN, 6), 256>>>(Qr, Qi, Kr, Ki, Vr, Vi);
    gram_mma_kernel<<<dim3(4, 16, BHN), 256>>>();
    attn_mma_kernel<<<dim3(8, BHN), 256>>>(out);
}

// round 15
// speedup vs baseline: 1.2571x; 1.0217x over previous
#include <cuda_runtime.h>
#include <cuda_bf16.h>
#include <stdint.h>
#include <math.h>

#define BHN 32          // B*H
#define LN 1024
#define DN 64
#define LMAXN 2048
#define NF 4
#define PARTN (BHN * NF * LN)   // 131072
#define PI_F 3.14159265358979323846f

// ---------------- device scratch (static allocation only) ----------------
__device__ __nv_bfloat16 g_gram[(size_t)BHN * LN * LN];  // 64 MB
__device__ __nv_bfloat16 g_qk[4][(size_t)BHN * 16 * 4096]; // bf16 swizzled tiles qr,qi,kr,ki
__device__ float g_a[NF * LN];
__device__ float g_p1[(size_t)8 * PARTN];             // s1 partials, slot-major (8 slots)
__device__ float g_epr[LN * DN];
__device__ float g_epi[LN * DN];
__device__ __nv_bfloat16 g_vtr[(size_t)BHN * DN * LN];
__device__ __nv_bfloat16 g_vti[(size_t)BHN * DN * LN];
__device__ float g_cspr[16 * BHN * DN];
__device__ float g_cspi[16 * BHN * DN];

__device__ __forceinline__ uint32_t smem_u32(const void* p) {
    uint32_t a;
    asm("{ .reg .u64 t; cvta.to.shared.u64 t, %1; cvt.u32.u64 %0, t; }" : "=r"(a) : "l"(p));
    return a;
}
__device__ __forceinline__ void sts32(uint32_t a, uint32_t v) {
    asm volatile("st.shared.b32 [%0], %1;" :: "r"(a), "r"(v));
}

#define LDSM_X4(r, a) \
    asm volatile("ldmatrix.sync.aligned.m8n8.x4.shared.b16 {%0,%1,%2,%3}, [%4];" \
        : "=r"((r)[0]), "=r"((r)[1]), "=r"((r)[2]), "=r"((r)[3]) : "r"(a))
#define MMA16816(d, a, b) \
    asm volatile("mma.sync.aligned.m16n8k16.row.col.f32.bf16.bf16.f32 " \
        "{%0,%1,%2,%3},{%4,%5,%6,%7},{%8,%9},{%0,%1,%2,%3};" \
        : "+f"((d)[0]), "+f"((d)[1]), "+f"((d)[2]), "+f"((d)[3]) \
        : "r"((a)[0]), "r"((a)[1]), "r"((a)[2]), "r"((a)[3]), "r"((b)[0]), "r"((b)[1]))
#define CPASYNC16(dst, src) \
    asm volatile("cp.async.cg.shared.global [%0], [%1], 16;" :: "r"(dst), "l"(src))
#define CPCOMMIT() asm volatile("cp.async.commit_group;" ::: "memory")
#define CPWAIT0()  asm volatile("cp.async.wait_group 0;" ::: "memory")
#define CPWAIT1()  asm volatile("cp.async.wait_group 1;" ::: "memory")

// ------- fused convert: Q/K bf16 tiles, V^T + colsum, AND prep (z=5) -------
__global__ __launch_bounds__(256) void convert_kernel(
    const float* __restrict__ Qr, const float* __restrict__ Qi,
    const float* __restrict__ Kr, const float* __restrict__ Ki,
    const float* __restrict__ Vr, const float* __restrict__ Vi) {
    __shared__ float sr[64][65], si[64][65];
    __shared__ float csr4[4][64], csi4[4][64];
    __shared__ float red[256];
    __shared__ float sCR[2], sCI[2];
    int tile = blockIdx.x, bh = blockIdx.y, arr = blockIdx.z;
    int tid = threadIdx.x;
    if (arr < 4) {
        // fp32 -> swizzled bf16 tiles for Q/K
        const float* src = (arr == 0 ? Qr : arr == 1 ? Qi : arr == 2 ? Kr : Ki)
                           + ((size_t)bh * LN + (size_t)tile * 64) * DN;
        char* dst = (char*)(g_qk[arr] + ((size_t)(bh * 16 + tile)) * 4096);
#pragma unroll
        for (int k = 0; k < 4; k++) {
            int i = tid + k * 256;
            int row = i >> 4, c4 = i & 15;
            float4 v = *(const float4*)(src + row * 64 + c4 * 4);
            uint32_t p0, p1;
            asm("cvt.rn.bf16x2.f32 %0, %1, %2;" : "=r"(p0) : "f"(v.y), "f"(v.x));
            asm("cvt.rn.bf16x2.f32 %0, %1, %2;" : "=r"(p1) : "f"(v.w), "f"(v.z));
            uint32_t off = (uint32_t)(row * 128 + c4 * 8);
            off ^= ((uint32_t)(row & 7) << 4);
            *(uint32_t*)(dst + off) = p0;
            *(uint32_t*)(dst + off + 4) = p1;
        }
        return;
    }
    if (arr == 5) {
        // ---- prep slice ----
        // Expert pattern, factorized: ep(l,d) = E(l) * e^{i*pd}.
        // E(l) = sum_j e^{i f_j t_l}  -> 24 sincos per l (2 l's per block),
        // then per (l,d): 1 sincos + 4 FMA.  Exact (fp32 reassoc only).
        int blk = bh * 16 + tile;            // 0..511, 2 l's per block
        if (tid < 2) {
            int l = blk * 2 + tid;
            float t = 2.f * PI_F * (float)l / (float)(LMAXN - 1);
            float cr = 0.f, ciA = 0.f;
            for (int i = 0; i < 8; i++) {
                float base = 0.1f * (float)i;
#pragma unroll
                for (int a = 0; a < 3; a++) {
                    float fr = (0.3f - 0.1f * (float)a) + base;
                    float s, c;
                    sincosf(fr * t, &s, &c);
                    cr += c;
                    ciA += s;
                }
            }
            sCR[tid] = cr;
            sCI[tid] = ciA;
        }
        __syncthreads();
        if (tid < 128) {
            int ll = tid >> 6, d = tid & 63;
            int l = blk * 2 + ll;
            float pd = 2.f * PI_F * (float)d / (float)DN;
            float sp, cp;
            sincosf(pd, &sp, &cp);
            const float C = (1.f / sqrtf((float)LMAXN)) / (sqrtf(3.f) * sqrtf(8.f));
            float CR = sCR[ll], CI = sCI[ll];
            g_epr[l * DN + d] = (CR * cp - CI * sp) * C;
            g_epi[l * DN + d] = (CI * cp + CR * sp) * C;
        }
        // freq-pattern blocks: tile<4, bh==0 (block-wide reduction)
        if (bh == 0 && tile < NF) {
            const float freqs[NF] = {1.0f, 0.5f, 0.25f, 0.1f};
            int f = tile;
            float step = 2.f * PI_F * freqs[f] / (float)(LMAXN - 1);
            float s = 0.f;
            for (int j = tid; j < LMAXN; j += 256) {
                float t = step * (float)j;
                s += 3.f + 2.f * cosf(t) + 2.f * cosf(0.5f * t) + 2.f * cosf(1.5f * t);
            }
            red[tid] = s;
            __syncthreads();
            for (int o = 128; o > 0; o >>= 1) {
                if (tid < o) red[tid] += red[tid + o];
                __syncthreads();
            }
            float norm2 = red[0];
            for (int l = tid; l < LN; l += 256) {
                float t = step * (float)l;
                float v = 3.f + 2.f * cosf(t) + 2.f * cosf(0.5f * t) + 2.f * cosf(1.5f * t);
                v = fmaxf(v, 0.f);
                g_a[f * LN + l] = sqrtf(v / norm2);
            }
        }
        return;
    }
    // arr == 4: V^T bf16 precompute + colsum partials
    int mt = tile;
    const float* vrb = Vr + ((size_t)bh * LN + (size_t)mt * 64) * DN;
    const float* vib = Vi + ((size_t)bh * LN + (size_t)mt * 64) * DN;
#pragma unroll
    for (int k = 0; k < 16; k++) {
        int i = tid + k * 256;
        int m = i >> 6, d = i & 63;
        sr[m][d] = vrb[i];
        si[m][d] = vib[i];
    }
    __syncthreads();
#pragma unroll
    for (int k = 0; k < 8; k++) {
        int i = tid + k * 256;
        int d = i >> 5, mp = i & 31, m = mp * 2;
        uint32_t pr, pi;
        asm("cvt.rn.bf16x2.f32 %0, %1, %2;" : "=r"(pr) : "f"(sr[m + 1][d]), "f"(sr[m][d]));
        asm("cvt.rn.bf16x2.f32 %0, %1, %2;" : "=r"(pi) : "f"(si[m + 1][d]), "f"(si[m][d]));
        size_t o = (size_t)bh * DN * LN + (size_t)d * LN + mt * 64 + m;
        *(uint32_t*)&g_vtr[o] = pr;
        *(uint32_t*)&g_vti[o] = pi;
    }
    {
        int d = tid & 63, seg = tid >> 6;
        float aR = 0.f, aI = 0.f;
#pragma unroll
        for (int j = 0; j < 16; j++) {
            aR += sr[seg * 16 + j][d];
            aI += si[seg * 16 + j][d];
        }
        csr4[seg][d] = aR; csi4[seg][d] = aI;
    }
    __syncthreads();
    if (tid < 64) {
        int d = tid;
        g_cspr[(mt * BHN + bh) * DN + d] = csr4[0][d] + csr4[1][d] + csr4[2][d] + csr4[3][d];
        g_cspi[(mt * BHN + bh) * DN + d] = csi4[0][d] + csi4[1][d] + csi4[2][d] + csi4[3][d];
    }
}

// ---- 8KB tile prefetch: 2 cp.async.16B per thread (256 thr) ----
__device__ __forceinline__ void prefetch_tile(uint32_t dst, const char* src, int tid) {
#pragma unroll
    for (int i = 0; i < 2; i++) {
        int o = (tid + i * 256) * 16;
        CPASYNC16(dst + o, src + o);
    }
}

// ---------------- A: gram; s1 moment computed ON the tensor core ----------
__global__ __launch_bounds__(256, 2) void gram_mma_kernel() {
    __shared__ __align__(16) uint32_t s_q[2][2048];      // qr, qi tiles
    __shared__ __align__(16) uint32_t s_k[2][2][2048];   // [buf][kr/ki]
    __shared__ float sAm[NF][256];

    int tid = threadIdx.x;
    int lane = tid & 31, w = tid >> 5;
    int wr = w >> 1, wc = w & 1;
    int mtg = blockIdx.x, lt = blockIdx.y, bh = blockIdx.z;

    const char* qrt = (const char*)(g_qk[0] + ((size_t)(bh * 16 + lt)) * 4096);
    const char* qit = (const char*)(g_qk[1] + ((size_t)(bh * 16 + lt)) * 4096);
    const char* krb = (const char*)(g_qk[2] + ((size_t)(bh * 16 + mtg * 4)) * 4096);
    const char* kib = (const char*)(g_qk[3] + ((size_t)(bh * 16 + mtg * 4)) * 4096);

    uint32_t aq0 = smem_u32(s_q[0]), aq1 = smem_u32(s_q[1]);

    prefetch_tile(aq0, qrt, tid);
    prefetch_tile(aq1, qit, tid);
    prefetch_tile(smem_u32(s_k[0][0]), krb, tid);
    prefetch_tile(smem_u32(s_k[0][1]), kib, tid);
    CPCOMMIT();
#pragma unroll
    for (int i = tid; i < NF * 256; i += 256)
        sAm[i >> 8][i & 255] = g_a[(i >> 8) * LN + mtg * 256 + (i & 255)];
    CPWAIT0();
    __syncthreads();

    int l16 = lane & 15, ac = lane >> 4;
    uint32_t aR[4][4], aI[4][4];
#pragma unroll
    for (int ks = 0; ks < 4; ks++) {
        int row = wr * 16 + l16;
        uint32_t off = (uint32_t)(row * 128 + ac * 16 + ks * 32);
        uint32_t sw = off ^ ((uint32_t)(row & 7) << 4);
        LDSM_X4(aR[ks], aq0 + sw);
        LDSM_X4(aI[ks], aq1 + sw);
    }

    int b_row = ((lane >> 4) << 3) + (lane & 7);
    int b_kh = (lane >> 3) & 1;
    int qrow = lane >> 2, qcol = (lane & 3) * 2;
    int fq = qrow;
    bool act = fq < NF;

    float sacc[4] = {0.f, 0.f, 0.f, 0.f};

    for (int it = 0; it < 4; it++) {
        int mt = mtg * 4 + it;
        if (it > 0) CPWAIT0();
        __syncthreads();
        if (it < 3) {
            prefetch_tile(smem_u32(s_k[(it + 1) & 1][0]), krb + (size_t)(it + 1) * 8192, tid);
            prefetch_tile(smem_u32(s_k[(it + 1) & 1][1]), kib + (size_t)(it + 1) * 8192, tid);
            CPCOMMIT();
        }

        uint32_t akr = smem_u32(s_k[it & 1][0]), aki = smem_u32(s_k[it & 1][1]);
        float cr[4][4] = {}, ci[4][4] = {};
#pragma unroll
        for (int ks = 0; ks < 4; ks++) {
            uint32_t bR[8], bI[8], bIn[8];
#pragma unroll
            for (int p = 0; p < 2; p++) {
                int row = wc * 32 + p * 16 + b_row;
                uint32_t off = (uint32_t)(row * 128 + b_kh * 16 + ks * 32);
                uint32_t sw = off ^ ((uint32_t)(row & 7) << 4);
                LDSM_X4(bR + p * 4, akr + sw);
                LDSM_X4(bI + p * 4, aki + sw);
            }
#pragma unroll
            for (int j = 0; j < 8; j++) bIn[j] = bI[j] ^ 0x80008000u;
#pragma unroll
            for (int ni = 0; ni < 4; ni++) {
                MMA16816(cr[ni], aR[ks], (bR + ni * 2));
                MMA16816(cr[ni], aI[ks], (bIn + ni * 2));
                MMA16816(ci[ni], aR[ks], (bI + ni * 2));
                MMA16816(ci[ni], aI[ks], (bR + ni * 2));
            }
        }

        __nv_bfloat16* gb = g_gram + (size_t)bh * LN * LN;
        int r0 = lt * 64 + wr * 16 + qrow;
#pragma unroll
        for (int ks2 = 0; ks2 < 2; ks2++) {
            uint32_t Afrag[4];
#pragma unroll
            for (int nio = 0; nio < 2; nio++) {
                int ni = ks2 * 2 + nio;
                float mg[4];
#pragma unroll
                for (int j = 0; j < 4; j++) {
                    float c = cr[ni][j], d = ci[ni][j];
                    float m2 = c * c + d * d;
                    float s;
                    asm("sqrt.approx.f32 %0, %1;" : "=f"(s) : "f"(m2));
                    mg[j] = s * 0.125f;
                }
                uint32_t p01, p23;
                asm("cvt.rn.bf16x2.f32 %0, %1, %2;" : "=r"(p01) : "f"(mg[1]), "f"(mg[0]));
                asm("cvt.rn.bf16x2.f32 %0, %1, %2;" : "=r"(p23) : "f"(mg[3]), "f"(mg[2]));
                int mcol = mt * 64 + wc * 32 + ni * 8 + qcol;
                *(uint32_t*)(gb + (size_t)r0 * LN + mcol) = p01;
                *(uint32_t*)(gb + (size_t)(r0 + 8) * LN + mcol) = p23;
                Afrag[nio * 2 + 0] = p01;
                Afrag[nio * 2 + 1] = p23;
            }
            int mb = it * 64 + wc * 32 + ks2 * 16;
            float a0 = 0.f, a1 = 0.f, a2 = 0.f, a3 = 0.f;
            if (act) {
                a0 = sAm[fq][mb + qcol];     a1 = sAm[fq][mb + qcol + 1];
                a2 = sAm[fq][mb + qcol + 8]; a3 = sAm[fq][mb + qcol + 9];
            }
            uint32_t Bfrag[2];
            asm("cvt.rn.bf16x2.f32 %0, %1, %2;" : "=r"(Bfrag[0]) : "f"(a1), "f"(a0));
            asm("cvt.rn.bf16x2.f32 %0, %1, %2;" : "=r"(Bfrag[1]) : "f"(a3), "f"(a2));
            MMA16816(sacc, Afrag, Bfrag);
        }
    }

    if ((lane & 3) < 2) {
        int slot = mtg * 2 + wc;
        int r0 = lt * 64 + wr * 16 + qrow;
        size_t base = (size_t)slot * PARTN + (size_t)bh * NF * LN;
        g_p1[base + (size_t)qcol * LN + r0] = sacc[0];
        g_p1[base + (size_t)(qcol + 1) * LN + r0] = sacc[1];
        g_p1[base + (size_t)qcol * LN + r0 + 8] = sacc[2];
        g_p1[base + (size_t)(qcol + 1) * LN + r0 + 8] = sacc[3];
    }
}

// ---- Vt tile prefetch (64 d-rows, swizzled; 256 thr) ----
__device__ __forceinline__ void prefetch_vt(
    uint32_t dr, uint32_t di,
    const __nv_bfloat16* vtr, const __nv_bfloat16* vti, int mt, int tid) {
#pragma unroll
    for (int k = 0; k < 2; k++) {
        int i = tid + k * 256;           // 0..511
        int row = i >> 3, c16 = i & 7;
        uint32_t off = (uint32_t)(row * 128 + c16 * 16);
        uint32_t sw = off ^ ((uint32_t)(row & 7) << 4);
        CPASYNC16(dr + sw, (const char*)(vtr + (size_t)row * LN + mt * 64) + c16 * 16);
        CPASYNC16(di + sw, (const char*)(vti + (size_t)row * LN + mt * 64) + c16 * 16);
    }
}

// ---- g tile prefetch: 128 rows x 128B, plain layout (256 thr) ----
__device__ __forceinline__ void prefetch_g(
    uint32_t dst, const __nv_bfloat16* gb, int mt, int tid) {
#pragma unroll
    for (int k = 0; k < 4; k++) {
        int i = tid + k * 256;           // 0..1023
        int row = i >> 3, c16 = i & 7;
        CPASYNC16(dst + (uint32_t)(row * 128 + c16 * 16),
                  (const char*)(gb + (size_t)row * LN + mt * 64) + c16 * 16);
    }
}

// -------- C: 256 thr, 128 l-rows, g + Vt cp.async double-buffered (R11) ----
__global__ __launch_bounds__(256, 2) void attn_mma_kernel(float* __restrict__ out) {
    __shared__ __align__(16) uint32_t s_w[4096];        // dW bf16 128x64 swizzled
    __shared__ __align__(16) uint32_t s_vr[2][2048];
    __shared__ __align__(16) uint32_t s_vi[2][2048];
    __shared__ __align__(16) uint32_t s_g[2][4096];     // g tiles 128x64 bf16 plain
    __shared__ float s_c[NF][128];
    __shared__ float s_base[128];
    __shared__ float s_csr[64], s_csi[64];
    __shared__ float s_is[NF][128];

    int tid = threadIdx.x;
    int lane = tid & 31, w = tid >> 5;
    int wr = w >> 1, wc = w & 1;
    int lt2 = blockIdx.x, bh = blockIdx.y;

    uint32_t a_w = smem_u32(s_w);
    const __nv_bfloat16* vtr = g_vtr + (size_t)bh * DN * LN;
    const __nv_bfloat16* vti = g_vti + (size_t)bh * DN * LN;
    const __nv_bfloat16* gb = g_gram + (size_t)bh * LN * LN + (size_t)lt2 * 128 * LN;

    // prologue prefetch: g[0] + Vt[0]
    prefetch_g(smem_u32(s_g[0]), gb, 0, tid);
    prefetch_vt(smem_u32(s_vr[0]), smem_u32(s_vi[0]), vtr, vti, 0, tid);
    CPCOMMIT();

    // invS reduction
#pragma unroll
    for (int idx = tid; idx < NF * 128; idx += 256) {
        int f = idx >> 7, r = idx & 127;
        int lg = lt2 * 128 + r;
        const float* p = g_p1 + ((size_t)bh * NF + f) * LN + lg;
        float s1 = 0.f;
#pragma unroll
        for (int i = 0; i < 8; i++) s1 += p[(size_t)i * PARTN];
        float al = g_a[f * LN + lg];
        s_is[f][r] = 1.f / (1024.f + al * s1);
    }
    __syncthreads();
    if (tid < 128) {
        int lg = lt2 * 128 + tid;
        float b = 0.f;
#pragma unroll
        for (int f = 0; f < NF; f++) {
            float is = s_is[f][tid];
            s_c[f][tid] = is * g_a[f * LN + lg];
            b += is;
        }
        s_base[tid] = b;
    }
    if (tid >= 128 && tid < 192) {
        int d = tid - 128;
        float csR = 0.f, csI = 0.f;
#pragma unroll
        for (int m2 = 0; m2 < 16; m2++) {
            csR += g_cspr[(m2 * BHN + bh) * DN + d];
            csI += g_cspi[(m2 * BHN + bh) * DN + d];
        }
        s_csr[d] = csR;
        s_csi[d] = csI;
    }

    float accr[2][4][4] = {}, acci[2][4][4] = {};

    int l16 = lane & 15, ac = lane >> 4;
    int bm0 = (tid & 31) * 2, lgrp = tid >> 5;
    int b_nii = (lane >> 4) & 1, b_kh = (lane >> 3) & 1, b_l8 = lane & 7;

    for (int mt = 0; mt < 16; mt++) {
        __syncthreads();          // prior iteration's buffer reads done
        if (mt < 15) {
            prefetch_g(smem_u32(s_g[(mt + 1) & 1]), gb, mt + 1, tid);
            prefetch_vt(smem_u32(s_vr[(mt + 1) & 1]), smem_u32(s_vi[(mt + 1) & 1]),
                        vtr, vti, mt + 1, tid);
            CPCOMMIT();
            CPWAIT1();            // group(mt) complete
        } else {
            CPWAIT0();
        }
        __syncthreads();          // group(mt) data visible to all
        // ---- build dW tile from smem g ----
        {
            uint32_t sg = smem_u32(s_g[mt & 1]);
            float am0[NF], am1[NF];
#pragma unroll
            for (int f = 0; f < NF; f++) {
                am0[f] = g_a[f * LN + mt * 64 + bm0];
                am1[f] = g_a[f * LN + mt * 64 + bm0 + 1];
            }
#pragma unroll 4
            for (int li = 0; li < 16; li++) {
                int l = lgrp * 16 + li;
                float dot0 = 0.f, dot1 = 0.f;
#pragma unroll
                for (int f = 0; f < NF; f++) {
                    float c = s_c[f][l];
                    dot0 = fmaf(c, am0[f], dot0);
                    dot1 = fmaf(c, am1[f], dot1);
                }
                uint32_t gp;
                asm volatile("ld.shared.b32 %0, [%1];"
                             : "=r"(gp) : "r"(sg + (uint32_t)(l * 128 + bm0 * 2)));
                float2 gf = __bfloat1622float2(*(__nv_bfloat162*)&gp);
                float w0 = dot0 * gf.x;
                float w1 = dot1 * gf.y;
                uint32_t p;
                asm("cvt.rn.bf16x2.f32 %0, %1, %2;" : "=r"(p) : "f"(w1), "f"(w0));
                uint32_t off = (uint32_t)(l * 128 + bm0 * 2);
                uint32_t sw = off ^ ((uint32_t)(l & 7) << 4);
                sts32(a_w + sw, p);
            }
        }
        __syncthreads();          // s_w ready
        uint32_t avr = smem_u32(s_vr[mt & 1]), avi = smem_u32(s_vi[mt & 1]);
#pragma unroll
        for (int ks = 0; ks < 4; ks++) {
            uint32_t aW[2][4];
#pragma unroll
            for (int mi = 0; mi < 2; mi++) {
                int row = wr * 32 + mi * 16 + l16;
                uint32_t off = (uint32_t)(row * 128 + ac * 16 + ks * 32);
                uint32_t sw = off ^ ((uint32_t)(row & 7) << 4);
                LDSM_X4(aW[mi], a_w + sw);
            }
#pragma unroll
            for (int ni2 = 0; ni2 < 2; ni2++) {
                uint32_t bR[4], bI[4];
                int row = wc * 32 + ni2 * 16 + b_nii * 8 + b_l8;
                uint32_t off = (uint32_t)(row * 128 + b_kh * 16 + ks * 32);
                uint32_t sw = off ^ ((uint32_t)(row & 7) << 4);
                LDSM_X4(bR, avr + sw);
                LDSM_X4(bI, avi + sw);
#pragma unroll
                for (int mi = 0; mi < 2; mi++) {
#pragma unroll
                    for (int h = 0; h < 2; h++) {
                        int ni = ni2 * 2 + h;
                        MMA16816(accr[mi][ni], aW[mi], (bR + h * 2));
                        MMA16816(acci[mi][ni], aW[mi], (bI + h * 2));
                    }
                }
            }
        }
    }

    int qrow = lane >> 2, qcol = (lane & 3) * 2;
    const size_t imag_off = (size_t)BHN * LN * DN;
    float* ob = out + (size_t)bh * LN * DN;
#pragma unroll
    for (int mi = 0; mi < 2; mi++) {
#pragma unroll
        for (int half = 0; half < 2; half++) {
            int lrow = wr * 32 + mi * 16 + half * 8 + qrow;
            int lg = lt2 * 128 + lrow;
            float base = s_base[lrow];
#pragma unroll
            for (int ni = 0; ni < 4; ni++) {
                int d = wc * 32 + ni * 8 + qcol;
                float ar0 = fmaf(base, s_csr[d], accr[mi][ni][half * 2]) * 0.5f;
                float ai0 = fmaf(base, s_csi[d], acci[mi][ni][half * 2]) * 0.5f;
                float ar1 = fmaf(base, s_csr[d + 1], accr[mi][ni][half * 2 + 1]) * 0.5f;
                float ai1 = fmaf(base, s_csi[d + 1], acci[mi][ni][half * 2 + 1]) * 0.5f;
                float2 er = *(const float2*)(g_epr + lg * DN + d);
                float2 ei = *(const float2*)(g_epi + lg * DN + d);
                float2 oR, oI;
                oR.x = ar0 * er.x - ai0 * ei.x;
                oI.x = ar0 * ei.x + ai0 * er.x;
                oR.y = ar1 * er.y - ai1 * ei.y;
                oI.y = ar1 * ei.y + ai1 * er.y;
                *(float2*)(ob + (size_t)lg * DN + d) = oR;
                *(float2*)(ob + imag_off + (size_t)lg * DN + d) = oI;
            }
        }
    }
}

// ---------------- launcher ----------------
extern "C" void kernel_launch(void* const* d_in, const int* in_sizes, int n_in,
                              void* d_out, int out_size) {
    (void)in_sizes; (void)n_in; (void)out_size;
    const float* Qr = (const float*)d_in[0];
    const float* Qi = (const float*)d_in[1];
    const float* Kr = (const float*)d_in[2];
    const float* Ki = (const float*)d_in[3];
    const float* Vr = (const float*)d_in[4];
    const float* Vi = (const float*)d_in[5];
    float* out = (float*)d_out;

    convert_kernel<<<dim3(16, BHN, 6), 256>>>(Qr, Qi, Kr, Ki, Vr, Vi);
    gram_mma_kernel<<<dim3(4, 16, BHN), 256>>>();
    attn_mma_kernel<<<dim3(8, BHN), 256>>>(out);
}

// round 16
// speedup vs baseline: 1.3103x; 1.0424x over previous
#include <cuda_runtime.h>
#include <cuda_bf16.h>
#include <stdint.h>
#include <math.h>

#define BHN 32          // B*H
#define LN 1024
#define DN 64
#define LMAXN 2048
#define NF 4
#define PARTN (BHN * NF * LN)   // 131072
#define PI_F 3.14159265358979323846f

// ---------------- device scratch (static allocation only) ----------------
__device__ __nv_bfloat16 g_gram[(size_t)BHN * LN * LN];  // 64 MB
__device__ __nv_bfloat16 g_qk[4][(size_t)BHN * 16 * 4096]; // bf16 swizzled tiles qr,qi,kr,ki
__device__ float g_a[NF * LN];
__device__ float g_p1[(size_t)8 * PARTN];             // s1 partials, slot-major (8 slots)
__device__ float g_epr[LN * DN];
__device__ float g_epi[LN * DN];
__device__ __nv_bfloat16 g_vtr[(size_t)BHN * DN * LN];
__device__ __nv_bfloat16 g_vti[(size_t)BHN * DN * LN];
__device__ float g_cspr[16 * BHN * DN];
__device__ float g_cspi[16 * BHN * DN];

__device__ __forceinline__ uint32_t smem_u32(const void* p) {
    uint32_t a;
    asm("{ .reg .u64 t; cvta.to.shared.u64 t, %1; cvt.u32.u64 %0, t; }" : "=r"(a) : "l"(p));
    return a;
}
__device__ __forceinline__ void sts32(uint32_t a, uint32_t v) {
    asm volatile("st.shared.b32 [%0], %1;" :: "r"(a), "r"(v));
}

#define LDSM_X4(r, a) \
    asm volatile("ldmatrix.sync.aligned.m8n8.x4.shared.b16 {%0,%1,%2,%3}, [%4];" \
        : "=r"((r)[0]), "=r"((r)[1]), "=r"((r)[2]), "=r"((r)[3]) : "r"(a))
#define MMA16816(d, a, b) \
    asm volatile("mma.sync.aligned.m16n8k16.row.col.f32.bf16.bf16.f32 " \
        "{%0,%1,%2,%3},{%4,%5,%6,%7},{%8,%9},{%0,%1,%2,%3};" \
        : "+f"((d)[0]), "+f"((d)[1]), "+f"((d)[2]), "+f"((d)[3]) \
        : "r"((a)[0]), "r"((a)[1]), "r"((a)[2]), "r"((a)[3]), "r"((b)[0]), "r"((b)[1]))
#define CPASYNC16(dst, src) \
    asm volatile("cp.async.cg.shared.global [%0], [%1], 16;" :: "r"(dst), "l"(src))
#define CPCOMMIT() asm volatile("cp.async.commit_group;" ::: "memory")
#define CPWAIT0()  asm volatile("cp.async.wait_group 0;" ::: "memory")
#define CPWAIT1()  asm volatile("cp.async.wait_group 1;" ::: "memory")

// ------- convert: Q/K bf16 tiles (z<4) + g_a freq patterns (z==4) ----------
__global__ __launch_bounds__(256) void convert_kernel(
    const float* __restrict__ Qr, const float* __restrict__ Qi,
    const float* __restrict__ Kr, const float* __restrict__ Ki) {
    __shared__ float red[256];
    int tile = blockIdx.x, bh = blockIdx.y, arr = blockIdx.z;
    int tid = threadIdx.x;
    if (arr < 4) {
        const float* src = (arr == 0 ? Qr : arr == 1 ? Qi : arr == 2 ? Kr : Ki)
                           + ((size_t)bh * LN + (size_t)tile * 64) * DN;
        char* dst = (char*)(g_qk[arr] + ((size_t)(bh * 16 + tile)) * 4096);
#pragma unroll
        for (int k = 0; k < 4; k++) {
            int i = tid + k * 256;
            int row = i >> 4, c4 = i & 15;
            float4 v = *(const float4*)(src + row * 64 + c4 * 4);
            uint32_t p0, p1;
            asm("cvt.rn.bf16x2.f32 %0, %1, %2;" : "=r"(p0) : "f"(v.y), "f"(v.x));
            asm("cvt.rn.bf16x2.f32 %0, %1, %2;" : "=r"(p1) : "f"(v.w), "f"(v.z));
            uint32_t off = (uint32_t)(row * 128 + c4 * 8);
            off ^= ((uint32_t)(row & 7) << 4);
            *(uint32_t*)(dst + off) = p0;
            *(uint32_t*)(dst + off + 4) = p1;
        }
        return;
    }
    // z == 4: freq-pattern a_f[l] (only 4 active blocks)
    if (bh == 0 && tile < NF) {
        const float freqs[NF] = {1.0f, 0.5f, 0.25f, 0.1f};
        int f = tile;
        float step = 2.f * PI_F * freqs[f] / (float)(LMAXN - 1);
        float s = 0.f;
        for (int j = tid; j < LMAXN; j += 256) {
            float t = step * (float)j;
            s += 3.f + 2.f * cosf(t) + 2.f * cosf(0.5f * t) + 2.f * cosf(1.5f * t);
        }
        red[tid] = s;
        __syncthreads();
        for (int o = 128; o > 0; o >>= 1) {
            if (tid < o) red[tid] += red[tid + o];
            __syncthreads();
        }
        float norm2 = red[0];
        for (int l = tid; l < LN; l += 256) {
            float t = step * (float)l;
            float v = 3.f + 2.f * cosf(t) + 2.f * cosf(0.5f * t) + 2.f * cosf(1.5f * t);
            v = fmaxf(v, 0.f);
            g_a[f * LN + l] = sqrtf(v / norm2);
        }
    }
}

// ---- 8KB tile prefetch: 2 cp.async.16B per thread (256 thr) ----
__device__ __forceinline__ void prefetch_tile(uint32_t dst, const char* src, int tid) {
#pragma unroll
    for (int i = 0; i < 2; i++) {
        int o = (tid + i * 256) * 16;
        CPASYNC16(dst + o, src + o);
    }
}

// ---- smem union: gram tiles OR vt transpose buffers ----
union GramSmem {
    struct {
        uint32_t s_q[2][2048];
        uint32_t s_k[2][2][2048];
        float sAm[NF][256];
    } g;
    struct {
        float sr[64][65];
        float si[64][65];
        float csr4[4][64];
        float csi4[4][64];
        float sCR[2], sCI[2];
    } v;
};

// -------- A: gram (z<32) + fused V^T/colsum/expert slices (z>=32) ----------
__global__ __launch_bounds__(256, 2) void gram_mma_kernel(
    const float* __restrict__ Vr, const float* __restrict__ Vi) {
    __shared__ GramSmem smu;

    int tid = threadIdx.x;
    int bz = blockIdx.z;

    if (bz >= BHN) {
        // ---- V^T + colsum + expert-pattern slice ----
        int idx = (bz - BHN) * 64 + blockIdx.y * 4 + blockIdx.x;  // 0..511
        int mt = idx >> 5, bhv = idx & 31;
        const float* vrb = Vr + ((size_t)bhv * LN + (size_t)mt * 64) * DN;
        const float* vib = Vi + ((size_t)bhv * LN + (size_t)mt * 64) * DN;
#pragma unroll
        for (int k = 0; k < 16; k++) {
            int i = tid + k * 256;
            int m = i >> 6, d = i & 63;
            smu.v.sr[m][d] = vrb[i];
            smu.v.si[m][d] = vib[i];
        }
        // expert pattern: E(l) for the 2 l's of this block
        if (tid >= 224 && tid < 226) {
            int ll = tid - 224;
            int l = idx * 2 + ll;
            float t = 2.f * PI_F * (float)l / (float)(LMAXN - 1);
            float cr = 0.f, ciA = 0.f;
            for (int i = 0; i < 8; i++) {
                float base = 0.1f * (float)i;
#pragma unroll
                for (int a = 0; a < 3; a++) {
                    float fr = (0.3f - 0.1f * (float)a) + base;
                    float s, c;
                    sincosf(fr * t, &s, &c);
                    cr += c;
                    ciA += s;
                }
            }
            smu.v.sCR[ll] = cr;
            smu.v.sCI[ll] = ciA;
        }
        __syncthreads();
#pragma unroll
        for (int k = 0; k < 8; k++) {
            int i = tid + k * 256;
            int d = i >> 5, mp = i & 31, m = mp * 2;
            uint32_t pr, pi;
            asm("cvt.rn.bf16x2.f32 %0, %1, %2;" : "=r"(pr)
                : "f"(smu.v.sr[m + 1][d]), "f"(smu.v.sr[m][d]));
            asm("cvt.rn.bf16x2.f32 %0, %1, %2;" : "=r"(pi)
                : "f"(smu.v.si[m + 1][d]), "f"(smu.v.si[m][d]));
            size_t o = (size_t)bhv * DN * LN + (size_t)d * LN + mt * 64 + m;
            *(uint32_t*)&g_vtr[o] = pr;
            *(uint32_t*)&g_vti[o] = pi;
        }
        {
            int d = tid & 63, seg = tid >> 6;
            float aR = 0.f, aI = 0.f;
#pragma unroll
            for (int j = 0; j < 16; j++) {
                aR += smu.v.sr[seg * 16 + j][d];
                aI += smu.v.si[seg * 16 + j][d];
            }
            smu.v.csr4[seg][d] = aR;
            smu.v.csi4[seg][d] = aI;
        }
        // expert pattern output: (l,d) for 2 l's x 64 d
        if (tid < 128) {
            int ll = tid >> 6, d = tid & 63;
            int l = idx * 2 + ll;
            float pd = 2.f * PI_F * (float)d / (float)DN;
            float sp, cp;
            sincosf(pd, &sp, &cp);
            const float C = (1.f / sqrtf((float)LMAXN)) / (sqrtf(3.f) * sqrtf(8.f));
            float CR = smu.v.sCR[ll], CI = smu.v.sCI[ll];
            g_epr[l * DN + d] = (CR * cp - CI * sp) * C;
            g_epi[l * DN + d] = (CI * cp + CR * sp) * C;
        }
        __syncthreads();
        if (tid < 64) {
            int d = tid;
            g_cspr[(mt * BHN + bhv) * DN + d] =
                smu.v.csr4[0][d] + smu.v.csr4[1][d] + smu.v.csr4[2][d] + smu.v.csr4[3][d];
            g_cspi[(mt * BHN + bhv) * DN + d] =
                smu.v.csi4[0][d] + smu.v.csi4[1][d] + smu.v.csi4[2][d] + smu.v.csi4[3][d];
        }
        return;
    }

    // ---- gram path ----
    int lane = tid & 31, w = tid >> 5;
    int wr = w >> 1, wc = w & 1;
    int mtg = blockIdx.x, lt = blockIdx.y, bh = bz;

    const char* qrt = (const char*)(g_qk[0] + ((size_t)(bh * 16 + lt)) * 4096);
    const char* qit = (const char*)(g_qk[1] + ((size_t)(bh * 16 + lt)) * 4096);
    const char* krb = (const char*)(g_qk[2] + ((size_t)(bh * 16 + mtg * 4)) * 4096);
    const char* kib = (const char*)(g_qk[3] + ((size_t)(bh * 16 + mtg * 4)) * 4096);

    uint32_t aq0 = smem_u32(smu.g.s_q[0]), aq1 = smem_u32(smu.g.s_q[1]);

    prefetch_tile(aq0, qrt, tid);
    prefetch_tile(aq1, qit, tid);
    prefetch_tile(smem_u32(smu.g.s_k[0][0]), krb, tid);
    prefetch_tile(smem_u32(smu.g.s_k[0][1]), kib, tid);
    CPCOMMIT();
#pragma unroll
    for (int i = tid; i < NF * 256; i += 256)
        smu.g.sAm[i >> 8][i & 255] = g_a[(i >> 8) * LN + mtg * 256 + (i & 255)];
    CPWAIT0();
    __syncthreads();

    int l16 = lane & 15, ac = lane >> 4;
    uint32_t aR[4][4], aI[4][4];
#pragma unroll
    for (int ks = 0; ks < 4; ks++) {
        int row = wr * 16 + l16;
        uint32_t off = (uint32_t)(row * 128 + ac * 16 + ks * 32);
        uint32_t sw = off ^ ((uint32_t)(row & 7) << 4);
        LDSM_X4(aR[ks], aq0 + sw);
        LDSM_X4(aI[ks], aq1 + sw);
    }

    int b_row = ((lane >> 4) << 3) + (lane & 7);
    int b_kh = (lane >> 3) & 1;
    int qrow = lane >> 2, qcol = (lane & 3) * 2;
    int fq = qrow;
    bool act = fq < NF;

    float sacc[4] = {0.f, 0.f, 0.f, 0.f};

    for (int it = 0; it < 4; it++) {
        int mt = mtg * 4 + it;
        if (it > 0) CPWAIT0();
        __syncthreads();
        if (it < 3) {
            prefetch_tile(smem_u32(smu.g.s_k[(it + 1) & 1][0]), krb + (size_t)(it + 1) * 8192, tid);
            prefetch_tile(smem_u32(smu.g.s_k[(it + 1) & 1][1]), kib + (size_t)(it + 1) * 8192, tid);
            CPCOMMIT();
        }

        uint32_t akr = smem_u32(smu.g.s_k[it & 1][0]), aki = smem_u32(smu.g.s_k[it & 1][1]);
        float cr[4][4] = {}, ci[4][4] = {};
#pragma unroll
        for (int ks = 0; ks < 4; ks++) {
            uint32_t bR[8], bI[8], bIn[8];
#pragma unroll
            for (int p = 0; p < 2; p++) {
                int row = wc * 32 + p * 16 + b_row;
                uint32_t off = (uint32_t)(row * 128 + b_kh * 16 + ks * 32);
                uint32_t sw = off ^ ((uint32_t)(row & 7) << 4);
                LDSM_X4(bR + p * 4, akr + sw);
                LDSM_X4(bI + p * 4, aki + sw);
            }
#pragma unroll
            for (int j = 0; j < 8; j++) bIn[j] = bI[j] ^ 0x80008000u;
#pragma unroll
            for (int ni = 0; ni < 4; ni++) {
                MMA16816(cr[ni], aR[ks], (bR + ni * 2));
                MMA16816(cr[ni], aI[ks], (bIn + ni * 2));
                MMA16816(ci[ni], aR[ks], (bI + ni * 2));
                MMA16816(ci[ni], aI[ks], (bR + ni * 2));
            }
        }

        __nv_bfloat16* gb = g_gram + (size_t)bh * LN * LN;
        int r0 = lt * 64 + wr * 16 + qrow;
#pragma unroll
        for (int ks2 = 0; ks2 < 2; ks2++) {
            uint32_t Afrag[4];
#pragma unroll
            for (int nio = 0; nio < 2; nio++) {
                int ni = ks2 * 2 + nio;
                float mg[4];
#pragma unroll
                for (int j = 0; j < 4; j++) {
                    float c = cr[ni][j], d = ci[ni][j];
                    float m2 = c * c + d * d;
                    float s;
                    asm("sqrt.approx.f32 %0, %1;" : "=f"(s) : "f"(m2));
                    mg[j] = s * 0.125f;
                }
                uint32_t p01, p23;
                asm("cvt.rn.bf16x2.f32 %0, %1, %2;" : "=r"(p01) : "f"(mg[1]), "f"(mg[0]));
                asm("cvt.rn.bf16x2.f32 %0, %1, %2;" : "=r"(p23) : "f"(mg[3]), "f"(mg[2]));
                int mcol = mt * 64 + wc * 32 + ni * 8 + qcol;
                *(uint32_t*)(gb + (size_t)r0 * LN + mcol) = p01;
                *(uint32_t*)(gb + (size_t)(r0 + 8) * LN + mcol) = p23;
                Afrag[nio * 2 + 0] = p01;
                Afrag[nio * 2 + 1] = p23;
            }
            int mb = it * 64 + wc * 32 + ks2 * 16;
            float a0 = 0.f, a1 = 0.f, a2 = 0.f, a3 = 0.f;
            if (act) {
                a0 = smu.g.sAm[fq][mb + qcol];     a1 = smu.g.sAm[fq][mb + qcol + 1];
                a2 = smu.g.sAm[fq][mb + qcol + 8]; a3 = smu.g.sAm[fq][mb + qcol + 9];
            }
            uint32_t Bfrag[2];
            asm("cvt.rn.bf16x2.f32 %0, %1, %2;" : "=r"(Bfrag[0]) : "f"(a1), "f"(a0));
            asm("cvt.rn.bf16x2.f32 %0, %1, %2;" : "=r"(Bfrag[1]) : "f"(a3), "f"(a2));
            MMA16816(sacc, Afrag, Bfrag);
        }
    }

    if ((lane & 3) < 2) {
        int slot = mtg * 2 + wc;
        int r0 = lt * 64 + wr * 16 + qrow;
        size_t base = (size_t)slot * PARTN + (size_t)bh * NF * LN;
        g_p1[base + (size_t)qcol * LN + r0] = sacc[0];
        g_p1[base + (size_t)(qcol + 1) * LN + r0] = sacc[1];
        g_p1[base + (size_t)qcol * LN + r0 + 8] = sacc[2];
        g_p1[base + (size_t)(qcol + 1) * LN + r0 + 8] = sacc[3];
    }
}

// ---- Vt tile prefetch (64 d-rows, swizzled; 256 thr) ----
__device__ __forceinline__ void prefetch_vt(
    uint32_t dr, uint32_t di,
    const __nv_bfloat16* vtr, const __nv_bfloat16* vti, int mt, int tid) {
#pragma unroll
    for (int k = 0; k < 2; k++) {
        int i = tid + k * 256;           // 0..511
        int row = i >> 3, c16 = i & 7;
        uint32_t off = (uint32_t)(row * 128 + c16 * 16);
        uint32_t sw = off ^ ((uint32_t)(row & 7) << 4);
        CPASYNC16(dr + sw, (const char*)(vtr + (size_t)row * LN + mt * 64) + c16 * 16);
        CPASYNC16(di + sw, (const char*)(vti + (size_t)row * LN + mt * 64) + c16 * 16);
    }
}

// ---- g tile prefetch: 128 rows x 128B, plain layout (256 thr) ----
__device__ __forceinline__ void prefetch_g(
    uint32_t dst, const __nv_bfloat16* gb, int mt, int tid) {
#pragma unroll
    for (int k = 0; k < 4; k++) {
        int i = tid + k * 256;           // 0..1023
        int row = i >> 3, c16 = i & 7;
        CPASYNC16(dst + (uint32_t)(row * 128 + c16 * 16),
                  (const char*)(gb + (size_t)row * LN + mt * 64) + c16 * 16);
    }
}

// -------- C: 256 thr, 128 l-rows, g + Vt cp.async double-buffered (R11) ----
__global__ __launch_bounds__(256, 2) void attn_mma_kernel(float* __restrict__ out) {
    __shared__ __align__(16) uint32_t s_w[4096];        // dW bf16 128x64 swizzled
    __shared__ __align__(16) uint32_t s_vr[2][2048];
    __shared__ __align__(16) uint32_t s_vi[2][2048];
    __shared__ __align__(16) uint32_t s_g[2][4096];     // g tiles 128x64 bf16 plain
    __shared__ float s_c[NF][128];
    __shared__ float s_base[128];
    __shared__ float s_csr[64], s_csi[64];
    __shared__ float s_is[NF][128];

    int tid = threadIdx.x;
    int lane = tid & 31, w = tid >> 5;
    int wr = w >> 1, wc = w & 1;
    int lt2 = blockIdx.x, bh = blockIdx.y;

    uint32_t a_w = smem_u32(s_w);
    const __nv_bfloat16* vtr = g_vtr + (size_t)bh * DN * LN;
    const __nv_bfloat16* vti = g_vti + (size_t)bh * DN * LN;
    const __nv_bfloat16* gb = g_gram + (size_t)bh * LN * LN + (size_t)lt2 * 128 * LN;

    // prologue prefetch: g[0] + Vt[0]
    prefetch_g(smem_u32(s_g[0]), gb, 0, tid);
    prefetch_vt(smem_u32(s_vr[0]), smem_u32(s_vi[0]), vtr, vti, 0, tid);
    CPCOMMIT();

    // invS reduction
#pragma unroll
    for (int idx = tid; idx < NF * 128; idx += 256) {
        int f = idx >> 7, r = idx & 127;
        int lg = lt2 * 128 + r;
        const float* p = g_p1 + ((size_t)bh * NF + f) * LN + lg;
        float s1 = 0.f;
#pragma unroll
        for (int i = 0; i < 8; i++) s1 += p[(size_t)i * PARTN];
        float al = g_a[f * LN + lg];
        s_is[f][r] = 1.f / (1024.f + al * s1);
    }
    __syncthreads();
    if (tid < 128) {
        int lg = lt2 * 128 + tid;
        float b = 0.f;
#pragma unroll
        for (int f = 0; f < NF; f++) {
            float is = s_is[f][tid];
            s_c[f][tid] = is * g_a[f * LN + lg];
            b += is;
        }
        s_base[tid] = b;
    }
    if (tid >= 128 && tid < 192) {
        int d = tid - 128;
        float csR = 0.f, csI = 0.f;
#pragma unroll
        for (int m2 = 0; m2 < 16; m2++) {
            csR += g_cspr[(m2 * BHN + bh) * DN + d];
            csI += g_cspi[(m2 * BHN + bh) * DN + d];
        }
        s_csr[d] = csR;
        s_csi[d] = csI;
    }

    float accr[2][4][4] = {}, acci[2][4][4] = {};

    int l16 = lane & 15, ac = lane >> 4;
    int bm0 = (tid & 31) * 2, lgrp = tid >> 5;
    int b_nii = (lane >> 4) & 1, b_kh = (lane >> 3) & 1, b_l8 = lane & 7;

    for (int mt = 0; mt < 16; mt++) {
        __syncthreads();          // prior iteration's buffer reads done
        if (mt < 15) {
            prefetch_g(smem_u32(s_g[(mt + 1) & 1]), gb, mt + 1, tid);
            prefetch_vt(smem_u32(s_vr[(mt + 1) & 1]), smem_u32(s_vi[(mt + 1) & 1]),
                        vtr, vti, mt + 1, tid);
            CPCOMMIT();
            CPWAIT1();            // group(mt) complete
        } else {
            CPWAIT0();
        }
        __syncthreads();          // group(mt) data visible to all
        // ---- build dW tile from smem g ----
        {
            uint32_t sg = smem_u32(s_g[mt & 1]);
            float am0[NF], am1[NF];
#pragma unroll
            for (int f = 0; f < NF; f++) {
                am0[f] = g_a[f * LN + mt * 64 + bm0];
                am1[f] = g_a[f * LN + mt * 64 + bm0 + 1];
            }
#pragma unroll 4
            for (int li = 0; li < 16; li++) {
                int l = lgrp * 16 + li;
                float dot0 = 0.f, dot1 = 0.f;
#pragma unroll
                for (int f = 0; f < NF; f++) {
                    float c = s_c[f][l];
                    dot0 = fmaf(c, am0[f], dot0);
                    dot1 = fmaf(c, am1[f], dot1);
                }
                uint32_t gp;
                asm volatile("ld.shared.b32 %0, [%1];"
                             : "=r"(gp) : "r"(sg + (uint32_t)(l * 128 + bm0 * 2)));
                float2 gf = __bfloat1622float2(*(__nv_bfloat162*)&gp);
                float w0 = dot0 * gf.x;
                float w1 = dot1 * gf.y;
                uint32_t p;
                asm("cvt.rn.bf16x2.f32 %0, %1, %2;" : "=r"(p) : "f"(w1), "f"(w0));
                uint32_t off = (uint32_t)(l * 128 + bm0 * 2);
                uint32_t sw = off ^ ((uint32_t)(l & 7) << 4);
                sts32(a_w + sw, p);
            }
        }
        __syncthreads();          // s_w ready
        uint32_t avr = smem_u32(s_vr[mt & 1]), avi = smem_u32(s_vi[mt & 1]);
#pragma unroll
        for (int ks = 0; ks < 4; ks++) {
            uint32_t aW[2][4];
#pragma unroll
            for (int mi = 0; mi < 2; mi++) {
                int row = wr * 32 + mi * 16 + l16;
                uint32_t off = (uint32_t)(row * 128 + ac * 16 + ks * 32);
                uint32_t sw = off ^ ((uint32_t)(row & 7) << 4);
                LDSM_X4(aW[mi], a_w + sw);
            }
#pragma unroll
            for (int ni2 = 0; ni2 < 2; ni2++) {
                uint32_t bR[4], bI[4];
                int row = wc * 32 + ni2 * 16 + b_nii * 8 + b_l8;
                uint32_t off = (uint32_t)(row * 128 + b_kh * 16 + ks * 32);
                uint32_t sw = off ^ ((uint32_t)(row & 7) << 4);
                LDSM_X4(bR, avr + sw);
                LDSM_X4(bI, avi + sw);
#pragma unroll
                for (int mi = 0; mi < 2; mi++) {
#pragma unroll
                    for (int h = 0; h < 2; h++) {
                        int ni = ni2 * 2 + h;
                        MMA16816(accr[mi][ni], aW[mi], (bR + h * 2));
                        MMA16816(acci[mi][ni], aW[mi], (bI + h * 2));
                    }
                }
            }
        }
    }

    int qrow = lane >> 2, qcol = (lane & 3) * 2;
    const size_t imag_off = (size_t)BHN * LN * DN;
    float* ob = out + (size_t)bh * LN * DN;
#pragma unroll
    for (int mi = 0; mi < 2; mi++) {
#pragma unroll
        for (int half = 0; half < 2; half++) {
            int lrow = wr * 32 + mi * 16 + half * 8 + qrow;
            int lg = lt2 * 128 + lrow;
            float base = s_base[lrow];
#pragma unroll
            for (int ni = 0; ni < 4; ni++) {
                int d = wc * 32 + ni * 8 + qcol;
                float ar0 = fmaf(base, s_csr[d], accr[mi][ni][half * 2]) * 0.5f;
                float ai0 = fmaf(base, s_csi[d], acci[mi][ni][half * 2]) * 0.5f;
                float ar1 = fmaf(base, s_csr[d + 1], accr[mi][ni][half * 2 + 1]) * 0.5f;
                float ai1 = fmaf(base, s_csi[d + 1], acci[mi][ni][half * 2 + 1]) * 0.5f;
                float2 er = *(const float2*)(g_epr + lg * DN + d);
                float2 ei = *(const float2*)(g_epi + lg * DN + d);
                float2 oR, oI;
                oR.x = ar0 * er.x - ai0 * ei.x;
                oI.x = ar0 * ei.x + ai0 * er.x;
                oR.y = ar1 * er.y - ai1 * ei.y;
                oI.y = ar1 * ei.y + ai1 * er.y;
                *(float2*)(ob + (size_t)lg * DN + d) = oR;
                *(float2*)(ob + imag_off + (size_t)lg * DN + d) = oI;
            }
        }
    }
}

// ---------------- launcher ----------------
extern "C" void kernel_launch(void* const* d_in, const int* in_sizes, int n_in,
                              void* d_out, int out_size) {
    (void)in_sizes; (void)n_in; (void)out_size;
    const float* Qr = (const float*)d_in[0];
    const float* Qi = (const float*)d_in[1];
    const float* Kr = (const float*)d_in[2];
    const float* Ki = (const float*)d_in[3];
    const float* Vr = (const float*)d_in[4];
    const float* Vi = (const float*)d_in[5];
    float* out = (float*)d_out;

    convert_kernel<<<dim3(16, BHN, 5), 256>>>(Qr, Qi, Kr, Ki);
    gram_mma_kernel<<<dim3(4, 16, BHN + 8), 256>>>(Vr, Vi);
    attn_mma_kernel<<<dim3(8, BHN), 256>>>(out);
}